// round 10
// baseline (speedup 1.0000x reference)
#include <cuda_runtime.h>
#include <cuda_bf16.h>
#include <math.h>
#include <stdint.h>

// Problem constants
#define NN_MAX 50000
#define NE_MAX 400000
#define DIM 256
#define NHEAD 4

// ---------------- scratch (static __device__ arrays, no allocation) -------
__device__ __nv_bfloat16 g_node_projh[NN_MAX * 768];  // [q|k|v] per node (76.8MB)
__device__ __nv_bfloat16 g_edge_projh[NE_MAX * 768];  // [q|k|v] per edge (614MB)
__device__ float    g_scores[NE_MAX * NHEAD];    // exp(score)
__device__ float    g_denom[NN_MAX * NHEAD];     // segment sum of exp
__device__ float    g_attn_out[NN_MAX * DIM];
__device__ float    g_tmp[NN_MAX * DIM];
__device__ float    g_h1[NN_MAX * DIM];
__device__ float    g_ff[NN_MAX * 1024];
__device__ float    g_ff2[NN_MAX * DIM];
// transposed weights [N][K] K-major (built per launch)
__device__ float    g_wt_n[768 * 256];
__device__ float    g_wt_e[768 * 256];
__device__ float    g_wt_wo[256 * 256];
__device__ float    g_wt_f1[1024 * 256];
__device__ float    g_wt_f2[256 * 1024];
__device__ float    g_bias_n[768];

// ---------------- helpers --------------------------------------------------
__device__ __forceinline__ float gelu_exact(float x) {
    return 0.5f * x * (1.0f + erff(x * 0.70710678118654752440f));
}
__device__ __forceinline__ unsigned pack_bf16x2(float x, float y) {
    __nv_bfloat162 h = __float22bfloat162_rn(make_float2(x, y));
    return reinterpret_cast<unsigned&>(h);
}
__device__ __forceinline__ void mma_bf16(float* c, const unsigned* a,
                                         const unsigned* b) {
    asm volatile(
        "mma.sync.aligned.m16n8k16.row.col.f32.bf16.bf16.f32 "
        "{%0,%1,%2,%3}, {%4,%5,%6,%7}, {%8,%9}, {%0,%1,%2,%3};"
        : "+f"(c[0]), "+f"(c[1]), "+f"(c[2]), "+f"(c[3])
        : "r"(a[0]), "r"(a[1]), "r"(a[2]), "r"(a[3]),
          "r"(b[0]), "r"(b[1]));
}

// ---------------- zero scratch --------------------------------------------
__global__ void k_zero(int n_att, int n_d) {
    int i = blockIdx.x * blockDim.x + threadIdx.x;
    if (i < n_att) g_attn_out[i] = 0.0f;
    if (i < n_d) g_denom[i] = 0.0f;
}

// ---------------- weight transpose: Wt[n_off+n][k] = W[(row_off+k)*ldw + n]
__global__ void k_transpose(const float* __restrict__ W, int ldw, int row_off,
                            float* __restrict__ Wt, int K, int n_off) {
    __shared__ float tile[32][33];
    int n0 = blockIdx.x * 32, k0 = blockIdx.y * 32;
    int tx = threadIdx.x, ty = threadIdx.y;  // 32 x 8
#pragma unroll
    for (int i = ty; i < 32; i += 8)
        tile[i][tx] = W[(size_t)(row_off + k0 + i) * ldw + n0 + tx];
    __syncthreads();
#pragma unroll
    for (int i = ty; i < 32; i += 8)
        Wt[(size_t)(n_off + n0 + i) * K + k0 + tx] = tile[tx][i];
}

__global__ void k_biascat(const float* __restrict__ a, const float* __restrict__ b) {
    int i = blockIdx.x * blockDim.x + threadIdx.x;
    if (i < 256) g_bias_n[i] = a[i];
    else if (i < 768) g_bias_n[i] = b[i - 256];
}

// ---------------- bf16 tensor-core GEMM (m16n8k16) -------------------------
// C[M,N] = A[M,K] @ Wt^T + bias (+gelu). A fp32 [M,K]; Wt fp32 [N,K] row-major.
// fp32 accumulate. Out fp32 or bf16.
// Block 128x128, BK=32 bf16 k-chunk. 256 thr = 2x4 warps, warp tile 64x32.
#define BKE 32           // k elements per stage
#define KW  20           // row stride in 32-bit words (40 bf16) — conflict-free

__global__ __launch_bounds__(256)
void tgemm_bf(const float* __restrict__ A, int M, int K,
              const float* __restrict__ Wt, const float* __restrict__ bias,
              void* __restrict__ C, int N, int act, int obf16) {
    __shared__ __align__(16) unsigned As[128 * KW];   // [row][k/2] bf16x2
    __shared__ __align__(16) unsigned Bs[128 * KW];   // [ncol][k/2]

    const int cb = blockIdx.x * 128;
    const int rb = blockIdx.y * 128;

    const int t    = threadIdx.x;
    const int lane = t & 31;
    const int wid  = t >> 5;
    const int wm   = wid & 1;
    const int wn   = wid >> 1;
    const int g    = lane >> 2;
    const int tg   = lane & 3;

    // staging decomposition: idx -> row (idx>>3), float4-col ((idx&7)*4)
    const int s_row = t >> 3;          // 0..31 (+32 per it)
    const int s_c4  = (t & 7) * 4;     // fp32 col, multiple of 4

    float acc[4][4][4];
#pragma unroll
    for (int mt = 0; mt < 4; mt++)
#pragma unroll
        for (int nt = 0; nt < 4; nt++)
#pragma unroll
            for (int r = 0; r < 4; r++) acc[mt][nt][r] = 0.0f;

    const int NT = K / BKE;
    float4 av[4], bv[4];

    auto ldg = [&](int k0) {
#pragma unroll
        for (int it = 0; it < 4; it++) {
            int row = s_row + 32 * it;
            int grow = rb + row;
            av[it] = *(const float4*)(A + (size_t)(grow < M ? grow : 0) * K + k0 + s_c4);
            bv[it] = *(const float4*)(Wt + (size_t)(cb + row) * K + k0 + s_c4);
        }
    };
    auto sts = [&]() {
#pragma unroll
        for (int it = 0; it < 4; it++) {
            int row = s_row + 32 * it;
            As[row * KW + s_c4 / 2]     = pack_bf16x2(av[it].x, av[it].y);
            As[row * KW + s_c4 / 2 + 1] = pack_bf16x2(av[it].z, av[it].w);
            Bs[row * KW + s_c4 / 2]     = pack_bf16x2(bv[it].x, bv[it].y);
            Bs[row * KW + s_c4 / 2 + 1] = pack_bf16x2(bv[it].z, bv[it].w);
        }
    };

    ldg(0);
    sts();
    __syncthreads();

    for (int kt = 0; kt < NT; kt++) {
        if (kt + 1 < NT) ldg((kt + 1) * BKE);

#pragma unroll
        for (int ko = 0; ko < BKE / 2; ko += 8) {   // word offset 0, 8
            unsigned a[4][4];
#pragma unroll
            for (int mt = 0; mt < 4; mt++) {
                int ar = wm * 64 + mt * 16 + g;
                a[mt][0] = As[(ar    ) * KW + ko + tg    ];
                a[mt][1] = As[(ar + 8) * KW + ko + tg    ];
                a[mt][2] = As[(ar    ) * KW + ko + tg + 4];
                a[mt][3] = As[(ar + 8) * KW + ko + tg + 4];
            }
            unsigned b[4][2];
#pragma unroll
            for (int nt = 0; nt < 4; nt++) {
                int bc = wn * 32 + nt * 8 + g;
                b[nt][0] = Bs[bc * KW + ko + tg    ];
                b[nt][1] = Bs[bc * KW + ko + tg + 4];
            }
#pragma unroll
            for (int mt = 0; mt < 4; mt++)
#pragma unroll
                for (int nt = 0; nt < 4; nt++)
                    mma_bf16(acc[mt][nt], a[mt], b[nt]);
        }
        __syncthreads();
        if (kt + 1 < NT) {
            sts();
            __syncthreads();
        }
    }

    // epilogue: c0:(r,c) c1:(r,c+1) c2:(r+8,c) c3:(r+8,c+1), c = 2*tg
#pragma unroll
    for (int mt = 0; mt < 4; mt++) {
        int r0 = rb + wm * 64 + mt * 16 + g;
#pragma unroll
        for (int nt = 0; nt < 4; nt++) {
            int lcol = wn * 32 + nt * 8 + tg * 2;
            int ccol = cb + lcol;
            float v0 = acc[mt][nt][0], v1 = acc[mt][nt][1];
            float v2 = acc[mt][nt][2], v3 = acc[mt][nt][3];
            if (bias) {
                float bb0 = bias[lcol], bb1 = bias[lcol + 1];
                v0 += bb0; v1 += bb1; v2 += bb0; v3 += bb1;
            }
            if (act == 1) {
                v0 = gelu_exact(v0); v1 = gelu_exact(v1);
                v2 = gelu_exact(v2); v3 = gelu_exact(v3);
            }
            if (obf16) {
                __nv_bfloat16* Cb = (__nv_bfloat16*)C;
                if (r0 < M) {
                    unsigned p = pack_bf16x2(v0, v1);
                    *(unsigned*)(Cb + (size_t)r0 * N + ccol) = p;
                }
                if (r0 + 8 < M) {
                    unsigned p = pack_bf16x2(v2, v3);
                    *(unsigned*)(Cb + (size_t)(r0 + 8) * N + ccol) = p;
                }
            } else {
                float* Cf = (float*)C;
                if (r0 < M) {
                    Cf[(size_t)r0 * N + ccol]     = v0;
                    Cf[(size_t)r0 * N + ccol + 1] = v1;
                }
                if (r0 + 8 < M) {
                    Cf[(size_t)(r0 + 8) * N + ccol]     = v2;
                    Cf[(size_t)(r0 + 8) * N + ccol + 1] = v3;
                }
            }
        }
    }
}

// ------- per-edge scores + exp + segment-sum (max-free: |s| <~ 2) ---------
__device__ __forceinline__ float dot8add(uint4 qa, uint4 qb, uint4 ka, uint4 kb) {
    float s = 0.f;
    const __nv_bfloat162* q1 = (const __nv_bfloat162*)&qa;
    const __nv_bfloat162* q2 = (const __nv_bfloat162*)&qb;
    const __nv_bfloat162* k1 = (const __nv_bfloat162*)&ka;
    const __nv_bfloat162* k2 = (const __nv_bfloat162*)&kb;
#pragma unroll
    for (int j = 0; j < 4; j++) {
        float2 x1 = __bfloat1622float2(q1[j]);
        float2 x2 = __bfloat1622float2(q2[j]);
        float2 y1 = __bfloat1622float2(k1[j]);
        float2 y2 = __bfloat1622float2(k2[j]);
        s += (x1.x + x2.x) * (y1.x + y2.x) + (x1.y + x2.y) * (y1.y + y2.y);
    }
    return s;
}

__global__ void k_scores(const int* __restrict__ ei, int NE) {
    int w = (blockIdx.x * blockDim.x + threadIdx.x) >> 5;
    int lane = threadIdx.x & 31;
    if (w >= NE) return;
    int src = ei[w];
    int dst = ei[NE + w];
    const __nv_bfloat16* qn = g_node_projh + (size_t)src * 768;
    const __nv_bfloat16* kn = g_node_projh + (size_t)dst * 768 + 256;
    const __nv_bfloat16* qe = g_edge_projh + (size_t)w * 768;
    const __nv_bfloat16* ke = qe + 256;
    uint4 a = *(const uint4*)(qn + lane * 8);
    uint4 b = *(const uint4*)(qe + lane * 8);
    uint4 c = *(const uint4*)(kn + lane * 8);
    uint4 d = *(const uint4*)(ke + lane * 8);
    float s = dot8add(a, b, c, d);
#pragma unroll
    for (int off = 1; off < 8; off <<= 1)
        s += __shfl_xor_sync(0xffffffffu, s, off);
    if ((lane & 7) == 0) {
        int h = lane >> 3;
        float ex = expf(s * 0.125f);   // 1/sqrt(64); scores are O(1), no max needed
        g_scores[(size_t)w * 4 + h] = ex;
        atomicAdd(&g_denom[src * 4 + h], ex);
    }
}

// ---------------- attn * V scatter ----------------------------------------
__global__ void k_scatter(const int* __restrict__ ei, int NE) {
    int w = (blockIdx.x * blockDim.x + threadIdx.x) >> 5;
    int lane = threadIdx.x & 31;
    if (w >= NE) return;
    int src = ei[w];
    int dst = ei[NE + w];
    int h = lane >> 3;
    float aw = g_scores[(size_t)w * 4 + h] / g_denom[src * 4 + h];
    const __nv_bfloat16* vn = g_node_projh + (size_t)dst * 768 + 512;
    const __nv_bfloat16* ve = g_edge_projh + (size_t)w * 768 + 512;
    uint4 a = *(const uint4*)(vn + lane * 8);
    uint4 b = *(const uint4*)(ve + lane * 8);
    float* o = g_attn_out + (size_t)src * 256 + lane * 8;
    const __nv_bfloat162* v1 = (const __nv_bfloat162*)&a;
    const __nv_bfloat162* v2 = (const __nv_bfloat162*)&b;
#pragma unroll
    for (int j = 0; j < 4; j++) {
        float2 x1 = __bfloat1622float2(v1[j]);
        float2 x2 = __bfloat1622float2(v2[j]);
        atomicAdd(o + 2 * j,     aw * (x1.x + x2.x));
        atomicAdd(o + 2 * j + 1, aw * (x1.y + x2.y));
    }
}

// ---------------- layernorm (warp per row of 256) -------------------------
__global__ void k_ln(const float* __restrict__ x, const float* __restrict__ res,
                     const float* __restrict__ g, const float* __restrict__ b,
                     float* __restrict__ out, int M) {
    int w = (blockIdx.x * blockDim.x + threadIdx.x) >> 5;
    int lane = threadIdx.x & 31;
    if (w >= M) return;
    float v[8];
    float s = 0.f;
#pragma unroll
    for (int j = 0; j < 8; j++) {
        int i = lane + 32 * j;
        v[j] = x[(size_t)w * 256 + i] + res[(size_t)w * 256 + i];
        s += v[j];
    }
#pragma unroll
    for (int off = 16; off; off >>= 1) s += __shfl_xor_sync(0xffffffffu, s, off);
    float mu = s * (1.0f / 256.0f);
    float q = 0.f;
#pragma unroll
    for (int j = 0; j < 8; j++) { float d = v[j] - mu; q += d * d; }
#pragma unroll
    for (int off = 16; off; off >>= 1) q += __shfl_xor_sync(0xffffffffu, q, off);
    float rstd = rsqrtf(q * (1.0f / 256.0f) + 1e-5f);
#pragma unroll
    for (int j = 0; j < 8; j++) {
        int i = lane + 32 * j;
        out[(size_t)w * 256 + i] = (v[j] - mu) * rstd * g[i] + b[i];
    }
}

// ---------------- host launch ----------------------------------------------
extern "C" void kernel_launch(void* const* d_in, const int* in_sizes, int n_in,
                              void* d_out, int out_size) {
    const float* h_n   = (const float*)d_in[0];
    const float* h_e   = (const float*)d_in[1];
    const int*   ei    = (const int*)d_in[2];   // int32 (JAX x64 disabled)
    const float* Wq_w  = (const float*)d_in[3];
    const float* Wq_b  = (const float*)d_in[4];
    const float* Wkv_w = (const float*)d_in[5];
    const float* Wkv_b = (const float*)d_in[6];
    const float* Wo_w  = (const float*)d_in[7];
    const float* Wo_b  = (const float*)d_in[8];
    const float* ln1_g = (const float*)d_in[9];
    const float* ln1_b = (const float*)d_in[10];
    const float* f1w   = (const float*)d_in[11];
    const float* f1b   = (const float*)d_in[12];
    const float* f2w   = (const float*)d_in[13];
    const float* f2b   = (const float*)d_in[14];
    const float* ln2_g = (const float*)d_in[15];
    const float* ln2_b = (const float*)d_in[16];
    float* out = (float*)d_out;

    int NN = in_sizes[0] / DIM;
    int NE = in_sizes[1] / DIM;

    void *p_nph, *p_eph, *p_att, *p_tmp, *p_h1, *p_ff, *p_ff2;
    void *p_wtn, *p_wte, *p_wtwo, *p_wtf1, *p_wtf2, *p_bn;
    cudaGetSymbolAddress(&p_nph, g_node_projh);
    cudaGetSymbolAddress(&p_eph, g_edge_projh);
    cudaGetSymbolAddress(&p_att, g_attn_out);
    cudaGetSymbolAddress(&p_tmp, g_tmp);
    cudaGetSymbolAddress(&p_h1, g_h1);
    cudaGetSymbolAddress(&p_ff, g_ff);
    cudaGetSymbolAddress(&p_ff2, g_ff2);
    cudaGetSymbolAddress(&p_wtn, g_wt_n);
    cudaGetSymbolAddress(&p_wte, g_wt_e);
    cudaGetSymbolAddress(&p_wtwo, g_wt_wo);
    cudaGetSymbolAddress(&p_wtf1, g_wt_f1);
    cudaGetSymbolAddress(&p_wtf2, g_wt_f2);
    cudaGetSymbolAddress(&p_bn, g_bias_n);

    dim3 tb(32, 8);

    // 0. weight transposes to [N][K] K-major + bias concat
    k_transpose<<<dim3(8, 8), tb>>>(Wq_w, 256, 0, (float*)p_wtn, 256, 0);
    k_transpose<<<dim3(16, 8), tb>>>(Wkv_w, 512, 0, (float*)p_wtn, 256, 256);
    k_transpose<<<dim3(8, 8), tb>>>(Wq_w, 256, 256, (float*)p_wte, 256, 0);
    k_transpose<<<dim3(16, 8), tb>>>(Wkv_w, 512, 256, (float*)p_wte, 256, 256);
    k_transpose<<<dim3(8, 8), tb>>>(Wo_w, 256, 0, (float*)p_wtwo, 256, 0);
    k_transpose<<<dim3(32, 8), tb>>>(f1w, 1024, 0, (float*)p_wtf1, 256, 0);
    k_transpose<<<dim3(8, 32), tb>>>(f2w, 256, 0, (float*)p_wtf2, 1024, 0);
    k_biascat<<<3, 256>>>(Wq_b, Wkv_b);

    // 1. zero denom / scatter destination
    {
        int n_att = NN * DIM;
        int n_d = NN * NHEAD;
        k_zero<<<(n_att + 255) / 256, 256>>>(n_att, n_d);
    }

    // 2. node projections -> bf16 [q|k|v]
    tgemm_bf<<<dim3(6, (NN + 127) / 128), 256>>>(
        h_n, NN, 256, (const float*)p_wtn, (const float*)p_bn, p_nph, 768, 0, 1);

    // 3. edge projections -> bf16 [q|k|v] (no bias)
    tgemm_bf<<<dim3(6, (NE + 127) / 128), 256>>>(
        h_e, NE, 256, (const float*)p_wte, nullptr, p_eph, 768, 0, 1);

    // 4. per-edge scores + exp + segment sum
    k_scores<<<(NE + 7) / 8, 256>>>(ei, NE);

    // 5. attn-weighted V scatter
    k_scatter<<<(NE + 7) / 8, 256>>>(ei, NE);

    // 6. output projection Wo (fp32 out)
    tgemm_bf<<<dim3(2, (NN + 127) / 128), 256>>>(
        (const float*)p_att, NN, 256, (const float*)p_wtwo, Wo_b, p_tmp, 256, 0, 0);

    // 7. LN1(h_n + attn_proj)
    k_ln<<<(NN + 7) / 8, 256>>>(h_n, (const float*)p_tmp, ln1_g, ln1_b,
                                (float*)p_h1, NN);

    // 8. FFN1 + exact GELU (fp32 out)
    tgemm_bf<<<dim3(8, (NN + 127) / 128), 256>>>(
        (const float*)p_h1, NN, 256, (const float*)p_wtf1, f1b, p_ff, 1024, 1, 0);

    // 9. FFN2 (fp32 out, K=1024)
    tgemm_bf<<<dim3(2, (NN + 127) / 128), 256>>>(
        (const float*)p_ff, NN, 1024, (const float*)p_wtf2, f2b, p_ff2, 256, 0, 0);

    // 10. LN2(h1 + ff) -> output
    k_ln<<<(NN + 7) / 8, 256>>>((const float*)p_h1, (const float*)p_ff2,
                                ln2_g, ln2_b, out, NN);
}

// round 11
// speedup vs baseline: 1.2700x; 1.2700x over previous
#include <cuda_runtime.h>
#include <cuda_bf16.h>
#include <math.h>
#include <stdint.h>

// Problem constants
#define NN_MAX 50000
#define NE_MAX 400000
#define DIM 256
#define NHEAD 4

typedef __nv_bfloat16 bf16;

// ---------------- scratch (static __device__ arrays, no allocation) -------
__device__ bf16     g_hn_bf[NN_MAX * 256];       // h_n bf16
__device__ bf16     g_he_bf[NE_MAX * 256];       // h_e bf16
__device__ bf16     g_node_projh[NN_MAX * 768];  // [q|k|v] per node
__device__ bf16     g_edge_projh[NE_MAX * 768];  // [q|k|v] per edge
__device__ float    g_scores[NE_MAX * NHEAD];    // exp(score)
__device__ float    g_denom[NN_MAX * NHEAD];     // segment sum of exp
__device__ float    g_attn_out[NN_MAX * DIM];    // fp32 scatter dest
__device__ bf16     g_att_bf[NN_MAX * DIM];      // bf16 copy for Wo GEMM
__device__ float    g_tmp[NN_MAX * DIM];         // after Wo
__device__ float    g_h1[NN_MAX * DIM];          // after LN1 (fp32)
__device__ bf16     g_h1_bf[NN_MAX * DIM];       // after LN1 (bf16)
__device__ bf16     g_ff_bf[NN_MAX * 1024];      // after FFN1+gelu (bf16)
__device__ float    g_ff2[NN_MAX * DIM];         // after FFN2
// transposed weights [N][K] K-major, bf16 (built per launch)
__device__ bf16     g_wt_n[768 * 256];
__device__ bf16     g_wt_e[768 * 256];
__device__ bf16     g_wt_wo[256 * 256];
__device__ bf16     g_wt_f1[1024 * 256];
__device__ bf16     g_wt_f2[256 * 1024];
__device__ float    g_bias_n[768];

// ---------------- helpers --------------------------------------------------
__device__ __forceinline__ float gelu_exact(float x) {
    return 0.5f * x * (1.0f + erff(x * 0.70710678118654752440f));
}
__device__ __forceinline__ unsigned pack_bf16x2(float x, float y) {
    __nv_bfloat162 h = __float22bfloat162_rn(make_float2(x, y));
    return reinterpret_cast<unsigned&>(h);
}
__device__ __forceinline__ void mma_bf16(float* c, const unsigned* a,
                                         const unsigned* b) {
    asm volatile(
        "mma.sync.aligned.m16n8k16.row.col.f32.bf16.bf16.f32 "
        "{%0,%1,%2,%3}, {%4,%5,%6,%7}, {%8,%9}, {%0,%1,%2,%3};"
        : "+f"(c[0]), "+f"(c[1]), "+f"(c[2]), "+f"(c[3])
        : "r"(a[0]), "r"(a[1]), "r"(a[2]), "r"(a[3]),
          "r"(b[0]), "r"(b[1]));
}
__device__ __forceinline__ void ldm_x4(unsigned* r, unsigned addr) {
    asm volatile("ldmatrix.sync.aligned.m8n8.x4.shared.b16 {%0,%1,%2,%3}, [%4];"
                 : "=r"(r[0]), "=r"(r[1]), "=r"(r[2]), "=r"(r[3]) : "r"(addr));
}
__device__ __forceinline__ void ldm_x2(unsigned* r, unsigned addr) {
    asm volatile("ldmatrix.sync.aligned.m8n8.x2.shared.b16 {%0,%1}, [%2];"
                 : "=r"(r[0]), "=r"(r[1]) : "r"(addr));
}
__device__ __forceinline__ void cpa16(unsigned s, const void* g) {
    asm volatile("cp.async.ca.shared.global [%0], [%1], 16;"
                 :: "r"(s), "l"(g));
}
__device__ __forceinline__ void cpa_commit() {
    asm volatile("cp.async.commit_group;");
}
template <int N>
__device__ __forceinline__ void cpa_wait() {
    asm volatile("cp.async.wait_group %0;" :: "n"(N));
}

// ---------------- zero + convert -------------------------------------------
__global__ void k_zero(int n_att, int n_d) {
    int i = blockIdx.x * blockDim.x + threadIdx.x;
    if (i < n_att) g_attn_out[i] = 0.0f;
    if (i < n_d) g_denom[i] = 0.0f;
}
__global__ void k_cvt(const float* __restrict__ x, bf16* __restrict__ y, int n4) {
    int i = blockIdx.x * blockDim.x + threadIdx.x;
    if (i >= n4) return;
    float4 v = *(const float4*)(x + 4 * i);
    uint2 p;
    p.x = pack_bf16x2(v.x, v.y);
    p.y = pack_bf16x2(v.z, v.w);
    *(uint2*)(y + 4 * i) = p;
}

// -------- weight transpose to bf16: Wt[n_off+n][k] = W[(row_off+k)*ldw + n]
__global__ void k_transpose(const float* __restrict__ W, int ldw, int row_off,
                            bf16* __restrict__ Wt, int K, int n_off) {
    __shared__ float tile[32][33];
    int n0 = blockIdx.x * 32, k0 = blockIdx.y * 32;
    int tx = threadIdx.x, ty = threadIdx.y;  // 32 x 8
#pragma unroll
    for (int i = ty; i < 32; i += 8)
        tile[i][tx] = W[(size_t)(row_off + k0 + i) * ldw + n0 + tx];
    __syncthreads();
#pragma unroll
    for (int i = ty; i < 32; i += 8)
        Wt[(size_t)(n_off + n0 + i) * K + k0 + tx] = __float2bfloat16(tile[tx][i]);
}

__global__ void k_biascat(const float* __restrict__ a, const float* __restrict__ b) {
    int i = blockIdx.x * blockDim.x + threadIdx.x;
    if (i < 256) g_bias_n[i] = a[i];
    else if (i < 768) g_bias_n[i] = b[i - 256];
}

// ---------------- bf16 tensor-core GEMM (cp.async + ldmatrix) --------------
// C[M,N] = A[M,K] @ Wt^T + bias (+gelu). A bf16 [M,K]; Wt bf16 [N,K].
// Block 128x128, BK=32. 256 thr = 2x4 warps, warp tile 64x32.
// smem row stride 80B: 8 ldmatrix row-addresses hit 8 distinct bank groups.
#define RS 80                       // bytes per smem row (64 data + 16 pad)
#define STG (128 * RS)              // one matrix stage: 10240 B

__global__ __launch_bounds__(256)
void tgemm_bf(const bf16* __restrict__ A, int M, int K,
              const bf16* __restrict__ Wt, const float* __restrict__ bias,
              void* __restrict__ C, int N, int act, int obf16) {
    __shared__ __align__(16) char sA[2 * STG];
    __shared__ __align__(16) char sB[2 * STG];
    const unsigned aBase0 = (unsigned)__cvta_generic_to_shared(sA);
    const unsigned bBase0 = (unsigned)__cvta_generic_to_shared(sB);

    const int cb = blockIdx.x * 128;
    const int rb = blockIdx.y * 128;

    const int t    = threadIdx.x;
    const int lane = t & 31;
    const int wid  = t >> 5;
    const int wm   = wid & 1;
    const int wn   = wid >> 1;
    const int g    = lane >> 2;
    const int tg   = lane & 3;

    float acc[4][4][4];
#pragma unroll
    for (int mt = 0; mt < 4; mt++)
#pragma unroll
        for (int nt = 0; nt < 4; nt++)
#pragma unroll
            for (int r = 0; r < 4; r++) acc[mt][nt][r] = 0.0f;

    const int NT = K / 32;
    const int s_row = t >> 1;            // 0..127 (2 chunks per thread pass)
    const int s_c   = (t & 1) * 2;       // chunk pair base

    auto stage = [&](int kt) {
        int buf = kt & 1;
        int k0 = kt * 32;
        // 128 rows x 4 chunks of 16B = 512 cp.async; 256 threads x 2
#pragma unroll
        for (int cc = 0; cc < 2; cc++) {
            int row = s_row;
            int c = s_c + cc;
            int ga = rb + row; if (ga >= M) ga = M - 1;
            cpa16(aBase0 + buf * STG + row * RS + c * 16,
                  A + (size_t)ga * K + k0 + c * 8);
            cpa16(bBase0 + buf * STG + row * RS + c * 16,
                  Wt + (size_t)(cb + row) * K + k0 + c * 8);
        }
        cpa_commit();
    };

    stage(0);

    // lane-dependent ldmatrix address offsets (bytes)
    const unsigned aOff = (lane & 15) * RS + (lane >> 4) * 16;
    const unsigned bOff = (lane & 7) * RS + ((lane >> 3) & 1) * 16;

    for (int kt = 0; kt < NT; kt++) {
        if (kt + 1 < NT) { stage(kt + 1); cpa_wait<1>(); }
        else             { cpa_wait<0>(); }
        __syncthreads();

        const unsigned aB = aBase0 + (kt & 1) * STG;
        const unsigned bB = bBase0 + (kt & 1) * STG;
#pragma unroll
        for (int ko = 0; ko < 2; ko++) {
            unsigned a[4][4], b[4][2];
#pragma unroll
            for (int mt = 0; mt < 4; mt++)
                ldm_x4(a[mt], aB + (wm * 64 + mt * 16) * RS + aOff + ko * 32);
#pragma unroll
            for (int nt = 0; nt < 4; nt++)
                ldm_x2(b[nt], bB + (wn * 32 + nt * 8) * RS + bOff + ko * 32);
#pragma unroll
            for (int mt = 0; mt < 4; mt++)
#pragma unroll
                for (int nt = 0; nt < 4; nt++)
                    mma_bf16(acc[mt][nt], a[mt], b[nt]);
        }
        __syncthreads();
    }

    // epilogue: c0:(r,c) c1:(r,c+1) c2:(r+8,c) c3:(r+8,c+1), c = 2*tg
#pragma unroll
    for (int mt = 0; mt < 4; mt++) {
        int r0 = rb + wm * 64 + mt * 16 + g;
#pragma unroll
        for (int nt = 0; nt < 4; nt++) {
            int lcol = wn * 32 + nt * 8 + tg * 2;
            int ccol = cb + lcol;
            float v0 = acc[mt][nt][0], v1 = acc[mt][nt][1];
            float v2 = acc[mt][nt][2], v3 = acc[mt][nt][3];
            if (bias) {
                float bb0 = bias[lcol], bb1 = bias[lcol + 1];
                v0 += bb0; v1 += bb1; v2 += bb0; v3 += bb1;
            }
            if (act == 1) {
                v0 = gelu_exact(v0); v1 = gelu_exact(v1);
                v2 = gelu_exact(v2); v3 = gelu_exact(v3);
            }
            if (obf16) {
                bf16* Cb = (bf16*)C;
                if (r0 < M)
                    *(unsigned*)(Cb + (size_t)r0 * N + ccol) = pack_bf16x2(v0, v1);
                if (r0 + 8 < M)
                    *(unsigned*)(Cb + (size_t)(r0 + 8) * N + ccol) = pack_bf16x2(v2, v3);
            } else {
                float* Cf = (float*)C;
                if (r0 < M) {
                    Cf[(size_t)r0 * N + ccol]     = v0;
                    Cf[(size_t)r0 * N + ccol + 1] = v1;
                }
                if (r0 + 8 < M) {
                    Cf[(size_t)(r0 + 8) * N + ccol]     = v2;
                    Cf[(size_t)(r0 + 8) * N + ccol + 1] = v3;
                }
            }
        }
    }
}

// ------- per-edge scores + exp + segment-sum (max-free: |s| <~ 2) ---------
__device__ __forceinline__ float dot8add(uint4 qa, uint4 qb, uint4 ka, uint4 kb) {
    float s = 0.f;
    const __nv_bfloat162* q1 = (const __nv_bfloat162*)&qa;
    const __nv_bfloat162* q2 = (const __nv_bfloat162*)&qb;
    const __nv_bfloat162* k1 = (const __nv_bfloat162*)&ka;
    const __nv_bfloat162* k2 = (const __nv_bfloat162*)&kb;
#pragma unroll
    for (int j = 0; j < 4; j++) {
        float2 x1 = __bfloat1622float2(q1[j]);
        float2 x2 = __bfloat1622float2(q2[j]);
        float2 y1 = __bfloat1622float2(k1[j]);
        float2 y2 = __bfloat1622float2(k2[j]);
        s += (x1.x + x2.x) * (y1.x + y2.x) + (x1.y + x2.y) * (y1.y + y2.y);
    }
    return s;
}

__global__ void k_scores(const int* __restrict__ ei, int NE) {
    int w = (blockIdx.x * blockDim.x + threadIdx.x) >> 5;
    int lane = threadIdx.x & 31;
    if (w >= NE) return;
    int src = ei[w];
    int dst = ei[NE + w];
    const bf16* qn = g_node_projh + (size_t)src * 768;
    const bf16* kn = g_node_projh + (size_t)dst * 768 + 256;
    const bf16* qe = g_edge_projh + (size_t)w * 768;
    const bf16* ke = qe + 256;
    uint4 a = *(const uint4*)(qn + lane * 8);
    uint4 b = *(const uint4*)(qe + lane * 8);
    uint4 c = *(const uint4*)(kn + lane * 8);
    uint4 d = *(const uint4*)(ke + lane * 8);
    float s = dot8add(a, b, c, d);
#pragma unroll
    for (int off = 1; off < 8; off <<= 1)
        s += __shfl_xor_sync(0xffffffffu, s, off);
    if ((lane & 7) == 0) {
        int h = lane >> 3;
        float ex = expf(s * 0.125f);   // 1/sqrt(64); scores are O(1), no max needed
        g_scores[(size_t)w * 4 + h] = ex;
        atomicAdd(&g_denom[src * 4 + h], ex);
    }
}

// ---------------- attn * V scatter ----------------------------------------
__global__ void k_scatter(const int* __restrict__ ei, int NE) {
    int w = (blockIdx.x * blockDim.x + threadIdx.x) >> 5;
    int lane = threadIdx.x & 31;
    if (w >= NE) return;
    int src = ei[w];
    int dst = ei[NE + w];
    int h = lane >> 3;
    float aw = g_scores[(size_t)w * 4 + h] / g_denom[src * 4 + h];
    const bf16* vn = g_node_projh + (size_t)dst * 768 + 512;
    const bf16* ve = g_edge_projh + (size_t)w * 768 + 512;
    uint4 a = *(const uint4*)(vn + lane * 8);
    uint4 b = *(const uint4*)(ve + lane * 8);
    float* o = g_attn_out + (size_t)src * 256 + lane * 8;
    const __nv_bfloat162* v1 = (const __nv_bfloat162*)&a;
    const __nv_bfloat162* v2 = (const __nv_bfloat162*)&b;
#pragma unroll
    for (int j = 0; j < 4; j++) {
        float2 x1 = __bfloat1622float2(v1[j]);
        float2 x2 = __bfloat1622float2(v2[j]);
        atomicAdd(o + 2 * j,     aw * (x1.x + x2.x));
        atomicAdd(o + 2 * j + 1, aw * (x1.y + x2.y));
    }
}

// ------------- layernorm (warp per row of 256), optional bf16 copy --------
__global__ void k_ln(const float* __restrict__ x, const float* __restrict__ res,
                     const float* __restrict__ g, const float* __restrict__ b,
                     float* __restrict__ out, bf16* __restrict__ out_bf, int M) {
    int w = (blockIdx.x * blockDim.x + threadIdx.x) >> 5;
    int lane = threadIdx.x & 31;
    if (w >= M) return;
    float v[8];
    float s = 0.f;
#pragma unroll
    for (int j = 0; j < 8; j++) {
        int i = lane + 32 * j;
        v[j] = x[(size_t)w * 256 + i] + res[(size_t)w * 256 + i];
        s += v[j];
    }
#pragma unroll
    for (int off = 16; off; off >>= 1) s += __shfl_xor_sync(0xffffffffu, s, off);
    float mu = s * (1.0f / 256.0f);
    float q = 0.f;
#pragma unroll
    for (int j = 0; j < 8; j++) { float d = v[j] - mu; q += d * d; }
#pragma unroll
    for (int off = 16; off; off >>= 1) q += __shfl_xor_sync(0xffffffffu, q, off);
    float rstd = rsqrtf(q * (1.0f / 256.0f) + 1e-5f);
#pragma unroll
    for (int j = 0; j < 8; j++) {
        int i = lane + 32 * j;
        float y = (v[j] - mu) * rstd * g[i] + b[i];
        out[(size_t)w * 256 + i] = y;
        if (out_bf) out_bf[(size_t)w * 256 + i] = __float2bfloat16(y);
    }
}

// ---------------- host launch ----------------------------------------------
extern "C" void kernel_launch(void* const* d_in, const int* in_sizes, int n_in,
                              void* d_out, int out_size) {
    const float* h_n   = (const float*)d_in[0];
    const float* h_e   = (const float*)d_in[1];
    const int*   ei    = (const int*)d_in[2];   // int32 (JAX x64 disabled)
    const float* Wq_w  = (const float*)d_in[3];
    const float* Wq_b  = (const float*)d_in[4];
    const float* Wkv_w = (const float*)d_in[5];
    const float* Wkv_b = (const float*)d_in[6];
    const float* Wo_w  = (const float*)d_in[7];
    const float* Wo_b  = (const float*)d_in[8];
    const float* ln1_g = (const float*)d_in[9];
    const float* ln1_b = (const float*)d_in[10];
    const float* f1w   = (const float*)d_in[11];
    const float* f1b   = (const float*)d_in[12];
    const float* f2w   = (const float*)d_in[13];
    const float* f2b   = (const float*)d_in[14];
    const float* ln2_g = (const float*)d_in[15];
    const float* ln2_b = (const float*)d_in[16];
    float* out = (float*)d_out;

    int NN = in_sizes[0] / DIM;
    int NE = in_sizes[1] / DIM;

    void *p_hn, *p_he, *p_nph, *p_eph, *p_att, *p_attb, *p_tmp;
    void *p_h1, *p_h1b, *p_ffb, *p_ff2;
    void *p_wtn, *p_wte, *p_wtwo, *p_wtf1, *p_wtf2, *p_bn;
    cudaGetSymbolAddress(&p_hn, g_hn_bf);
    cudaGetSymbolAddress(&p_he, g_he_bf);
    cudaGetSymbolAddress(&p_nph, g_node_projh);
    cudaGetSymbolAddress(&p_eph, g_edge_projh);
    cudaGetSymbolAddress(&p_att, g_attn_out);
    cudaGetSymbolAddress(&p_attb, g_att_bf);
    cudaGetSymbolAddress(&p_tmp, g_tmp);
    cudaGetSymbolAddress(&p_h1, g_h1);
    cudaGetSymbolAddress(&p_h1b, g_h1_bf);
    cudaGetSymbolAddress(&p_ffb, g_ff_bf);
    cudaGetSymbolAddress(&p_ff2, g_ff2);
    cudaGetSymbolAddress(&p_wtn, g_wt_n);
    cudaGetSymbolAddress(&p_wte, g_wt_e);
    cudaGetSymbolAddress(&p_wtwo, g_wt_wo);
    cudaGetSymbolAddress(&p_wtf1, g_wt_f1);
    cudaGetSymbolAddress(&p_wtf2, g_wt_f2);
    cudaGetSymbolAddress(&p_bn, g_bias_n);

    dim3 tb(32, 8);

    // 0a. weight transposes to bf16 [N][K] + bias concat
    k_transpose<<<dim3(8, 8), tb>>>(Wq_w, 256, 0, (bf16*)p_wtn, 256, 0);
    k_transpose<<<dim3(16, 8), tb>>>(Wkv_w, 512, 0, (bf16*)p_wtn, 256, 256);
    k_transpose<<<dim3(8, 8), tb>>>(Wq_w, 256, 256, (bf16*)p_wte, 256, 0);
    k_transpose<<<dim3(16, 8), tb>>>(Wkv_w, 512, 256, (bf16*)p_wte, 256, 256);
    k_transpose<<<dim3(8, 8), tb>>>(Wo_w, 256, 0, (bf16*)p_wtwo, 256, 0);
    k_transpose<<<dim3(32, 8), tb>>>(f1w, 1024, 0, (bf16*)p_wtf1, 256, 0);
    k_transpose<<<dim3(8, 32), tb>>>(f2w, 256, 0, (bf16*)p_wtf2, 1024, 0);
    k_biascat<<<3, 256>>>(Wq_b, Wkv_b);

    // 0b. activation conversions fp32 -> bf16
    k_cvt<<<(NN * 64 + 255) / 256, 256>>>(h_n, (bf16*)p_hn, NN * 64);
    k_cvt<<<(NE * 64 + 255) / 256, 256>>>(h_e, (bf16*)p_he, NE * 64);

    // 1. zero denom / scatter destination
    k_zero<<<(NN * DIM + 255) / 256, 256>>>(NN * DIM, NN * NHEAD);

    // 2. node projections -> bf16 [q|k|v]
    tgemm_bf<<<dim3(6, (NN + 127) / 128), 256>>>(
        (const bf16*)p_hn, NN, 256, (const bf16*)p_wtn, (const float*)p_bn,
        p_nph, 768, 0, 1);

    // 3. edge projections -> bf16 [q|k|v] (no bias)
    tgemm_bf<<<dim3(6, (NE + 127) / 128), 256>>>(
        (const bf16*)p_he, NE, 256, (const bf16*)p_wte, nullptr, p_eph, 768, 0, 1);

    // 4. per-edge scores + exp + segment sum
    k_scores<<<(NE + 7) / 8, 256>>>(ei, NE);

    // 5. attn-weighted V scatter
    k_scatter<<<(NE + 7) / 8, 256>>>(ei, NE);

    // 5b. convert attention output to bf16
    k_cvt<<<(NN * 64 + 255) / 256, 256>>>((const float*)p_att, (bf16*)p_attb,
                                          NN * 64);

    // 6. output projection Wo (fp32 out)
    tgemm_bf<<<dim3(2, (NN + 127) / 128), 256>>>(
        (const bf16*)p_attb, NN, 256, (const bf16*)p_wtwo, Wo_b, p_tmp, 256, 0, 0);

    // 7. LN1(h_n + attn_proj) -> fp32 + bf16
    k_ln<<<(NN + 7) / 8, 256>>>(h_n, (const float*)p_tmp, ln1_g, ln1_b,
                                (float*)p_h1, (bf16*)p_h1b, NN);

    // 8. FFN1 + exact GELU -> bf16
    tgemm_bf<<<dim3(8, (NN + 127) / 128), 256>>>(
        (const bf16*)p_h1b, NN, 256, (const bf16*)p_wtf1, f1b, p_ffb, 1024, 1, 1);

    // 9. FFN2 (fp32 out, K=1024)
    tgemm_bf<<<dim3(2, (NN + 127) / 128), 256>>>(
        (const bf16*)p_ffb, NN, 1024, (const bf16*)p_wtf2, f2b, p_ff2, 256, 0, 0);

    // 10. LN2(h1 + ff) -> output
    k_ln<<<(NN + 7) / 8, 256>>>((const float*)p_h1, (const float*)p_ff2,
                                ln2_g, ln2_b, out, nullptr, NN);
}

// round 12
// speedup vs baseline: 1.5156x; 1.1934x over previous
#include <cuda_runtime.h>
#include <cuda_bf16.h>
#include <math.h>
#include <stdint.h>

// Problem constants
#define NN_MAX 50000
#define NE_MAX 400000
#define DIM 256
#define NHEAD 4

typedef __nv_bfloat16 bf16;

// ---------------- scratch (static __device__ arrays, no allocation) -------
__device__ bf16     g_hn_bf[NN_MAX * 256];       // h_n bf16
__device__ bf16     g_he_bf[NE_MAX * 256];       // h_e bf16
__device__ bf16     g_node_projh[NN_MAX * 768];  // [q|k|v] per node
__device__ bf16     g_edge_projh[NE_MAX * 768];  // [q|k|v] per edge
__device__ float    g_scores[NE_MAX * NHEAD];    // exp(score)
__device__ float    g_denom[NN_MAX * NHEAD];     // segment sum of exp
__device__ bf16     g_att_bf[NN_MAX * DIM];      // bf16 scatter dest (feeds Wo)
__device__ float    g_tmp[NN_MAX * DIM];         // after Wo
__device__ float    g_h1[NN_MAX * DIM];          // after LN1 (fp32)
__device__ bf16     g_h1_bf[NN_MAX * DIM];       // after LN1 (bf16)
__device__ bf16     g_ff_bf[NN_MAX * 1024];      // after FFN1+gelu (bf16)
__device__ float    g_ff2[NN_MAX * DIM];         // after FFN2
// transposed weights [N][K] K-major, bf16 (built per launch)
__device__ bf16     g_wt_n[768 * 256];
__device__ bf16     g_wt_e[768 * 256];
__device__ bf16     g_wt_wo[256 * 256];
__device__ bf16     g_wt_f1[1024 * 256];
__device__ bf16     g_wt_f2[256 * 1024];
__device__ float    g_bias_n[768];

// ---------------- helpers --------------------------------------------------
__device__ __forceinline__ float gelu_exact(float x) {
    return 0.5f * x * (1.0f + erff(x * 0.70710678118654752440f));
}
__device__ __forceinline__ unsigned pack_bf16x2(float x, float y) {
    __nv_bfloat162 h = __float22bfloat162_rn(make_float2(x, y));
    return reinterpret_cast<unsigned&>(h);
}
__device__ __forceinline__ void mma_bf16(float* c, const unsigned* a,
                                         const unsigned* b) {
    asm volatile(
        "mma.sync.aligned.m16n8k16.row.col.f32.bf16.bf16.f32 "
        "{%0,%1,%2,%3}, {%4,%5,%6,%7}, {%8,%9}, {%0,%1,%2,%3};"
        : "+f"(c[0]), "+f"(c[1]), "+f"(c[2]), "+f"(c[3])
        : "r"(a[0]), "r"(a[1]), "r"(a[2]), "r"(a[3]),
          "r"(b[0]), "r"(b[1]));
}
__device__ __forceinline__ void ldm_x4(unsigned* r, unsigned addr) {
    asm volatile("ldmatrix.sync.aligned.m8n8.x4.shared.b16 {%0,%1,%2,%3}, [%4];"
                 : "=r"(r[0]), "=r"(r[1]), "=r"(r[2]), "=r"(r[3]) : "r"(addr));
}
__device__ __forceinline__ void ldm_x2(unsigned* r, unsigned addr) {
    asm volatile("ldmatrix.sync.aligned.m8n8.x2.shared.b16 {%0,%1}, [%2];"
                 : "=r"(r[0]), "=r"(r[1]) : "r"(addr));
}
__device__ __forceinline__ void cpa16(unsigned s, const void* g) {
    asm volatile("cp.async.ca.shared.global [%0], [%1], 16;"
                 :: "r"(s), "l"(g));
}
__device__ __forceinline__ void cpa_commit() {
    asm volatile("cp.async.commit_group;");
}
template <int N>
__device__ __forceinline__ void cpa_wait() {
    asm volatile("cp.async.wait_group %0;" :: "n"(N));
}

// ---------------- zero + convert -------------------------------------------
__global__ void k_zero(int n_attw, int n_d) {
    int i = blockIdx.x * blockDim.x + threadIdx.x;
    if (i < n_attw) ((unsigned*)g_att_bf)[i] = 0u;   // bf16x2 zeros
    if (i < n_d) g_denom[i] = 0.0f;
}
__global__ void k_cvt(const float* __restrict__ x, bf16* __restrict__ y, int n4) {
    int i = blockIdx.x * blockDim.x + threadIdx.x;
    if (i >= n4) return;
    float4 v = *(const float4*)(x + 4 * i);
    uint2 p;
    p.x = pack_bf16x2(v.x, v.y);
    p.y = pack_bf16x2(v.z, v.w);
    *(uint2*)(y + 4 * i) = p;
}

// -------- weight transpose to bf16: Wt[n_off+n][k] = W[(row_off+k)*ldw + n]
__global__ void k_transpose(const float* __restrict__ W, int ldw, int row_off,
                            bf16* __restrict__ Wt, int K, int n_off) {
    __shared__ float tile[32][33];
    int n0 = blockIdx.x * 32, k0 = blockIdx.y * 32;
    int tx = threadIdx.x, ty = threadIdx.y;  // 32 x 8
#pragma unroll
    for (int i = ty; i < 32; i += 8)
        tile[i][tx] = W[(size_t)(row_off + k0 + i) * ldw + n0 + tx];
    __syncthreads();
#pragma unroll
    for (int i = ty; i < 32; i += 8)
        Wt[(size_t)(n_off + n0 + i) * K + k0 + tx] = __float2bfloat16(tile[tx][i]);
}

__global__ void k_biascat(const float* __restrict__ a, const float* __restrict__ b) {
    int i = blockIdx.x * blockDim.x + threadIdx.x;
    if (i < 256) g_bias_n[i] = a[i];
    else if (i < 768) g_bias_n[i] = b[i - 256];
}

// ---------------- bf16 tensor-core GEMM (4-stage cp.async + ldmatrix) ------
// C[M,N] = A[M,K] @ Wt^T + bias (+gelu). A bf16 [M,K]; Wt bf16 [N,K].
// Block 128x128, BK=32. 256 thr = 2x4 warps, warp tile 64x32.
// smem row stride 80B: ldmatrix row-addresses conflict-free.
#define RS 80                        // bytes per smem row (64 data + 16 pad)
#define MSTG (128 * RS)              // one matrix stage: 10240 B
#define PSTG (2 * MSTG)              // A+B stage pair: 20480 B
#define NSTAGE 4
#define GSM_BYTES (NSTAGE * PSTG)    // 81920 B dynamic smem

__global__ __launch_bounds__(256)
void tgemm_bf(const bf16* __restrict__ A, int M, int K,
              const bf16* __restrict__ Wt, const float* __restrict__ bias,
              void* __restrict__ C, int N, int act, int obf16) {
    extern __shared__ char dsm[];
    const unsigned base = (unsigned)__cvta_generic_to_shared(dsm);

    const int cb = blockIdx.x * 128;
    const int rb = blockIdx.y * 128;

    const int t    = threadIdx.x;
    const int lane = t & 31;
    const int wid  = t >> 5;
    const int wm   = wid & 1;
    const int wn   = wid >> 1;
    const int g    = lane >> 2;
    const int tg   = lane & 3;

    float acc[4][4][4];
#pragma unroll
    for (int mt = 0; mt < 4; mt++)
#pragma unroll
        for (int nt = 0; nt < 4; nt++)
#pragma unroll
            for (int r = 0; r < 4; r++) acc[mt][nt][r] = 0.0f;

    const int NT = K / 32;
    const int s_row = t >> 1;            // 0..127
    const int s_c   = (t & 1) * 2;       // 16B-chunk pair base

    auto stage = [&](int kt) {
        unsigned sb = base + (kt & (NSTAGE - 1)) * PSTG;
        int k0 = kt * 32;
        int ga = rb + s_row; if (ga >= M) ga = M - 1;
#pragma unroll
        for (int cc = 0; cc < 2; cc++) {
            int c = s_c + cc;
            cpa16(sb + s_row * RS + c * 16, A + (size_t)ga * K + k0 + c * 8);
            cpa16(sb + MSTG + s_row * RS + c * 16,
                  Wt + (size_t)(cb + s_row) * K + k0 + c * 8);
        }
        cpa_commit();
    };

    // prologue: fill 3 stages
    stage(0);
    if (NT > 1) stage(1); else cpa_commit();
    if (NT > 2) stage(2); else cpa_commit();

    // lane-dependent ldmatrix address offsets (bytes)
    const unsigned aOff = (lane & 15) * RS + (lane >> 4) * 16;
    const unsigned bOff = (lane & 7) * RS + ((lane >> 3) & 1) * 16;

    for (int kt = 0; kt < NT; kt++) {
        cpa_wait<2>();      // stage kt complete (uniform: one commit per iter)
        __syncthreads();    // visibility + all warps done with stage kt-4's buf
        if (kt + 3 < NT) stage(kt + 3); else cpa_commit();

        const unsigned aB = base + (kt & (NSTAGE - 1)) * PSTG;
        const unsigned bB = aB + MSTG;
#pragma unroll
        for (int ko = 0; ko < 2; ko++) {
            unsigned a[4][4], b[4][2];
#pragma unroll
            for (int mt = 0; mt < 4; mt++)
                ldm_x4(a[mt], aB + (wm * 64 + mt * 16) * RS + aOff + ko * 32);
#pragma unroll
            for (int nt = 0; nt < 4; nt++)
                ldm_x2(b[nt], bB + (wn * 32 + nt * 8) * RS + bOff + ko * 32);
#pragma unroll
            for (int mt = 0; mt < 4; mt++)
#pragma unroll
                for (int nt = 0; nt < 4; nt++)
                    mma_bf16(acc[mt][nt], a[mt], b[nt]);
        }
    }

    // epilogue: c0:(r,c) c1:(r,c+1) c2:(r+8,c) c3:(r+8,c+1), c = 2*tg
#pragma unroll
    for (int mt = 0; mt < 4; mt++) {
        int r0 = rb + wm * 64 + mt * 16 + g;
#pragma unroll
        for (int nt = 0; nt < 4; nt++) {
            int lcol = wn * 32 + nt * 8 + tg * 2;
            int ccol = cb + lcol;
            float v0 = acc[mt][nt][0], v1 = acc[mt][nt][1];
            float v2 = acc[mt][nt][2], v3 = acc[mt][nt][3];
            if (bias) {
                float bb0 = bias[lcol], bb1 = bias[lcol + 1];
                v0 += bb0; v1 += bb1; v2 += bb0; v3 += bb1;
            }
            if (act == 1) {
                v0 = gelu_exact(v0); v1 = gelu_exact(v1);
                v2 = gelu_exact(v2); v3 = gelu_exact(v3);
            }
            if (obf16) {
                bf16* Cb = (bf16*)C;
                if (r0 < M)
                    *(unsigned*)(Cb + (size_t)r0 * N + ccol) = pack_bf16x2(v0, v1);
                if (r0 + 8 < M)
                    *(unsigned*)(Cb + (size_t)(r0 + 8) * N + ccol) = pack_bf16x2(v2, v3);
            } else {
                float* Cf = (float*)C;
                if (r0 < M) {
                    Cf[(size_t)r0 * N + ccol]     = v0;
                    Cf[(size_t)r0 * N + ccol + 1] = v1;
                }
                if (r0 + 8 < M) {
                    Cf[(size_t)(r0 + 8) * N + ccol]     = v2;
                    Cf[(size_t)(r0 + 8) * N + ccol + 1] = v3;
                }
            }
        }
    }
}

// ------- per-edge scores + exp + segment-sum (max-free: |s| <~ 2) ---------
__device__ __forceinline__ float dot8add(uint4 qa, uint4 qb, uint4 ka, uint4 kb) {
    float s = 0.f;
    const __nv_bfloat162* q1 = (const __nv_bfloat162*)&qa;
    const __nv_bfloat162* q2 = (const __nv_bfloat162*)&qb;
    const __nv_bfloat162* k1 = (const __nv_bfloat162*)&ka;
    const __nv_bfloat162* k2 = (const __nv_bfloat162*)&kb;
#pragma unroll
    for (int j = 0; j < 4; j++) {
        float2 x1 = __bfloat1622float2(q1[j]);
        float2 x2 = __bfloat1622float2(q2[j]);
        float2 y1 = __bfloat1622float2(k1[j]);
        float2 y2 = __bfloat1622float2(k2[j]);
        s += (x1.x + x2.x) * (y1.x + y2.x) + (x1.y + x2.y) * (y1.y + y2.y);
    }
    return s;
}

__global__ void k_scores(const int* __restrict__ ei, int NE) {
    int w = (blockIdx.x * blockDim.x + threadIdx.x) >> 5;
    int lane = threadIdx.x & 31;
    if (w >= NE) return;
    int src = ei[w];
    int dst = ei[NE + w];
    const bf16* qn = g_node_projh + (size_t)src * 768;
    const bf16* kn = g_node_projh + (size_t)dst * 768 + 256;
    const bf16* qe = g_edge_projh + (size_t)w * 768;
    const bf16* ke = qe + 256;
    uint4 a = *(const uint4*)(qn + lane * 8);
    uint4 b = *(const uint4*)(qe + lane * 8);
    uint4 c = *(const uint4*)(kn + lane * 8);
    uint4 d = *(const uint4*)(ke + lane * 8);
    float s = dot8add(a, b, c, d);
#pragma unroll
    for (int off = 1; off < 8; off <<= 1)
        s += __shfl_xor_sync(0xffffffffu, s, off);
    if ((lane & 7) == 0) {
        int h = lane >> 3;
        float ex = expf(s * 0.125f);   // 1/sqrt(64); scores are O(1), no max needed
        g_scores[(size_t)w * 4 + h] = ex;
        atomicAdd(&g_denom[src * 4 + h], ex);
    }
}

// ---------------- attn * V scatter (bf16x2 atomics) ------------------------
__global__ void k_scatter(const int* __restrict__ ei, int NE) {
    int w = (blockIdx.x * blockDim.x + threadIdx.x) >> 5;
    int lane = threadIdx.x & 31;
    if (w >= NE) return;
    int src = ei[w];
    int dst = ei[NE + w];
    int h = lane >> 3;
    float aw = g_scores[(size_t)w * 4 + h] / g_denom[src * 4 + h];
    const bf16* vn = g_node_projh + (size_t)dst * 768 + 512;
    const bf16* ve = g_edge_projh + (size_t)w * 768 + 512;
    uint4 a = *(const uint4*)(vn + lane * 8);
    uint4 b = *(const uint4*)(ve + lane * 8);
    __nv_bfloat162* o = (__nv_bfloat162*)(g_att_bf + (size_t)src * 256 + lane * 8);
    const __nv_bfloat162* v1 = (const __nv_bfloat162*)&a;
    const __nv_bfloat162* v2 = (const __nv_bfloat162*)&b;
#pragma unroll
    for (int j = 0; j < 4; j++) {
        float2 x1 = __bfloat1622float2(v1[j]);
        float2 x2 = __bfloat1622float2(v2[j]);
        __nv_bfloat162 add = __float22bfloat162_rn(
            make_float2(aw * (x1.x + x2.x), aw * (x1.y + x2.y)));
        atomicAdd(o + j, add);
    }
}

// ------------- layernorm (warp per row of 256), optional bf16 copy --------
__global__ void k_ln(const float* __restrict__ x, const float* __restrict__ res,
                     const float* __restrict__ g, const float* __restrict__ b,
                     float* __restrict__ out, bf16* __restrict__ out_bf, int M) {
    int w = (blockIdx.x * blockDim.x + threadIdx.x) >> 5;
    int lane = threadIdx.x & 31;
    if (w >= M) return;
    float v[8];
    float s = 0.f;
#pragma unroll
    for (int j = 0; j < 8; j++) {
        int i = lane + 32 * j;
        v[j] = x[(size_t)w * 256 + i] + res[(size_t)w * 256 + i];
        s += v[j];
    }
#pragma unroll
    for (int off = 16; off; off >>= 1) s += __shfl_xor_sync(0xffffffffu, s, off);
    float mu = s * (1.0f / 256.0f);
    float q = 0.f;
#pragma unroll
    for (int j = 0; j < 8; j++) { float d = v[j] - mu; q += d * d; }
#pragma unroll
    for (int off = 16; off; off >>= 1) q += __shfl_xor_sync(0xffffffffu, q, off);
    float rstd = rsqrtf(q * (1.0f / 256.0f) + 1e-5f);
#pragma unroll
    for (int j = 0; j < 8; j++) {
        int i = lane + 32 * j;
        float y = (v[j] - mu) * rstd * g[i] + b[i];
        out[(size_t)w * 256 + i] = y;
        if (out_bf) out_bf[(size_t)w * 256 + i] = __float2bfloat16(y);
    }
}

// ---------------- host launch ----------------------------------------------
extern "C" void kernel_launch(void* const* d_in, const int* in_sizes, int n_in,
                              void* d_out, int out_size) {
    const float* h_n   = (const float*)d_in[0];
    const float* h_e   = (const float*)d_in[1];
    const int*   ei    = (const int*)d_in[2];   // int32 (JAX x64 disabled)
    const float* Wq_w  = (const float*)d_in[3];
    const float* Wq_b  = (const float*)d_in[4];
    const float* Wkv_w = (const float*)d_in[5];
    const float* Wkv_b = (const float*)d_in[6];
    const float* Wo_w  = (const float*)d_in[7];
    const float* Wo_b  = (const float*)d_in[8];
    const float* ln1_g = (const float*)d_in[9];
    const float* ln1_b = (const float*)d_in[10];
    const float* f1w   = (const float*)d_in[11];
    const float* f1b   = (const float*)d_in[12];
    const float* f2w   = (const float*)d_in[13];
    const float* f2b   = (const float*)d_in[14];
    const float* ln2_g = (const float*)d_in[15];
    const float* ln2_b = (const float*)d_in[16];
    float* out = (float*)d_out;

    int NN = in_sizes[0] / DIM;
    int NE = in_sizes[1] / DIM;

    cudaFuncSetAttribute(tgemm_bf, cudaFuncAttributeMaxDynamicSharedMemorySize,
                         GSM_BYTES);

    void *p_hn, *p_he, *p_nph, *p_eph, *p_attb, *p_tmp;
    void *p_h1, *p_h1b, *p_ffb, *p_ff2;
    void *p_wtn, *p_wte, *p_wtwo, *p_wtf1, *p_wtf2, *p_bn;
    cudaGetSymbolAddress(&p_hn, g_hn_bf);
    cudaGetSymbolAddress(&p_he, g_he_bf);
    cudaGetSymbolAddress(&p_nph, g_node_projh);
    cudaGetSymbolAddress(&p_eph, g_edge_projh);
    cudaGetSymbolAddress(&p_attb, g_att_bf);
    cudaGetSymbolAddress(&p_tmp, g_tmp);
    cudaGetSymbolAddress(&p_h1, g_h1);
    cudaGetSymbolAddress(&p_h1b, g_h1_bf);
    cudaGetSymbolAddress(&p_ffb, g_ff_bf);
    cudaGetSymbolAddress(&p_ff2, g_ff2);
    cudaGetSymbolAddress(&p_wtn, g_wt_n);
    cudaGetSymbolAddress(&p_wte, g_wt_e);
    cudaGetSymbolAddress(&p_wtwo, g_wt_wo);
    cudaGetSymbolAddress(&p_wtf1, g_wt_f1);
    cudaGetSymbolAddress(&p_wtf2, g_wt_f2);
    cudaGetSymbolAddress(&p_bn, g_bias_n);

    dim3 tb(32, 8);

    // 0a. weight transposes to bf16 [N][K] + bias concat
    k_transpose<<<dim3(8, 8), tb>>>(Wq_w, 256, 0, (bf16*)p_wtn, 256, 0);
    k_transpose<<<dim3(16, 8), tb>>>(Wkv_w, 512, 0, (bf16*)p_wtn, 256, 256);
    k_transpose<<<dim3(8, 8), tb>>>(Wq_w, 256, 256, (bf16*)p_wte, 256, 0);
    k_transpose<<<dim3(16, 8), tb>>>(Wkv_w, 512, 256, (bf16*)p_wte, 256, 256);
    k_transpose<<<dim3(8, 8), tb>>>(Wo_w, 256, 0, (bf16*)p_wtwo, 256, 0);
    k_transpose<<<dim3(32, 8), tb>>>(f1w, 1024, 0, (bf16*)p_wtf1, 256, 0);
    k_transpose<<<dim3(8, 32), tb>>>(f2w, 256, 0, (bf16*)p_wtf2, 1024, 0);
    k_biascat<<<3, 256>>>(Wq_b, Wkv_b);

    // 0b. activation conversions fp32 -> bf16
    k_cvt<<<(NN * 64 + 255) / 256, 256>>>(h_n, (bf16*)p_hn, NN * 64);
    k_cvt<<<(NE * 64 + 255) / 256, 256>>>(h_e, (bf16*)p_he, NE * 64);

    // 1. zero denom / scatter destination (bf16, as uint words)
    k_zero<<<(NN * 128 + 255) / 256, 256>>>(NN * 128, NN * NHEAD);

    // 2. node projections -> bf16 [q|k|v]
    tgemm_bf<<<dim3(6, (NN + 127) / 128), 256, GSM_BYTES>>>(
        (const bf16*)p_hn, NN, 256, (const bf16*)p_wtn, (const float*)p_bn,
        p_nph, 768, 0, 1);

    // 3. edge projections -> bf16 [q|k|v] (no bias)
    tgemm_bf<<<dim3(6, (NE + 127) / 128), 256, GSM_BYTES>>>(
        (const bf16*)p_he, NE, 256, (const bf16*)p_wte, nullptr, p_eph, 768, 0, 1);

    // 4. per-edge scores + exp + segment sum
    k_scores<<<(NE + 7) / 8, 256>>>(ei, NE);

    // 5. attn-weighted V scatter (bf16x2 atomics into g_att_bf)
    k_scatter<<<(NE + 7) / 8, 256>>>(ei, NE);

    // 6. output projection Wo (fp32 out)
    tgemm_bf<<<dim3(2, (NN + 127) / 128), 256, GSM_BYTES>>>(
        (const bf16*)p_attb, NN, 256, (const bf16*)p_wtwo, Wo_b, p_tmp, 256, 0, 0);

    // 7. LN1(h_n + attn_proj) -> fp32 + bf16
    k_ln<<<(NN + 7) / 8, 256>>>(h_n, (const float*)p_tmp, ln1_g, ln1_b,
                                (float*)p_h1, (bf16*)p_h1b, NN);

    // 8. FFN1 + exact GELU -> bf16
    tgemm_bf<<<dim3(8, (NN + 127) / 128), 256, GSM_BYTES>>>(
        (const bf16*)p_h1b, NN, 256, (const bf16*)p_wtf1, f1b, p_ffb, 1024, 1, 1);

    // 9. FFN2 (fp32 out, K=1024)
    tgemm_bf<<<dim3(2, (NN + 127) / 128), 256, GSM_BYTES>>>(
        (const bf16*)p_ffb, NN, 1024, (const bf16*)p_wtf2, f2b, p_ff2, 256, 0, 0);

    // 10. LN2(h1 + ff) -> output
    k_ln<<<(NN + 7) / 8, 256>>>((const float*)p_h1, (const float*)p_ff2,
                                ln2_g, ln2_b, out, nullptr, NN);
}

// round 13
// speedup vs baseline: 1.5469x; 1.0206x over previous
#include <cuda_runtime.h>
#include <cuda_bf16.h>
#include <math.h>
#include <stdint.h>

// Problem constants
#define NN_MAX 50000
#define NE_MAX 400000
#define DIM 256
#define NHEAD 4

typedef __nv_bfloat16 bf16;

// ---------------- scratch (static __device__ arrays, no allocation) -------
__device__ bf16     g_hn_bf[NN_MAX * 256];       // h_n bf16
__device__ bf16     g_he_bf[NE_MAX * 256];       // h_e bf16
__device__ bf16     g_node_projh[NN_MAX * 768];  // [q|k|v] per node
__device__ bf16     g_edge_projh[NE_MAX * 768];  // [q|k|v] per edge
__device__ float    g_scores[NE_MAX * NHEAD];    // exp(score)
__device__ float    g_denom[NN_MAX * NHEAD];     // segment sum of exp
__device__ bf16     g_att_bf[NN_MAX * DIM];      // bf16 scatter dest (feeds Wo)
__device__ float    g_tmp[NN_MAX * DIM];         // after Wo
__device__ float    g_h1[NN_MAX * DIM];          // after LN1 (fp32)
__device__ bf16     g_h1_bf[NN_MAX * DIM];       // after LN1 (bf16)
__device__ bf16     g_ff_bf[NN_MAX * 1024];      // after FFN1+gelu (bf16)
__device__ float    g_ff2[NN_MAX * DIM];         // after FFN2
// transposed weights [N][K] K-major, bf16 (built per launch)
__device__ bf16     g_wt_n[768 * 256];
__device__ bf16     g_wt_e[768 * 256];
__device__ bf16     g_wt_wo[256 * 256];
__device__ bf16     g_wt_f1[1024 * 256];
__device__ bf16     g_wt_f2[256 * 1024];
__device__ float    g_bias_n[768];

// ---------------- helpers --------------------------------------------------
__device__ __forceinline__ float gelu_exact(float x) {
    return 0.5f * x * (1.0f + erff(x * 0.70710678118654752440f));
}
__device__ __forceinline__ unsigned pack_bf16x2(float x, float y) {
    __nv_bfloat162 h = __float22bfloat162_rn(make_float2(x, y));
    return reinterpret_cast<unsigned&>(h);
}
__device__ __forceinline__ void mma_bf16(float* c, const unsigned* a,
                                         const unsigned* b) {
    asm volatile(
        "mma.sync.aligned.m16n8k16.row.col.f32.bf16.bf16.f32 "
        "{%0,%1,%2,%3}, {%4,%5,%6,%7}, {%8,%9}, {%0,%1,%2,%3};"
        : "+f"(c[0]), "+f"(c[1]), "+f"(c[2]), "+f"(c[3])
        : "r"(a[0]), "r"(a[1]), "r"(a[2]), "r"(a[3]),
          "r"(b[0]), "r"(b[1]));
}
__device__ __forceinline__ void ldm_x4(unsigned* r, unsigned addr) {
    asm volatile("ldmatrix.sync.aligned.m8n8.x4.shared.b16 {%0,%1,%2,%3}, [%4];"
                 : "=r"(r[0]), "=r"(r[1]), "=r"(r[2]), "=r"(r[3]) : "r"(addr));
}
__device__ __forceinline__ void ldm_x2(unsigned* r, unsigned addr) {
    asm volatile("ldmatrix.sync.aligned.m8n8.x2.shared.b16 {%0,%1}, [%2];"
                 : "=r"(r[0]), "=r"(r[1]) : "r"(addr));
}
__device__ __forceinline__ void cpa16(unsigned s, const void* g) {
    asm volatile("cp.async.ca.shared.global [%0], [%1], 16;"
                 :: "r"(s), "l"(g));
}
__device__ __forceinline__ void cpa_commit() {
    asm volatile("cp.async.commit_group;");
}
template <int N>
__device__ __forceinline__ void cpa_wait() {
    asm volatile("cp.async.wait_group %0;" :: "n"(N));
}

// ---------------- fused prologue kernels -----------------------------------
__device__ __forceinline__ void transpose_tile(
    const float* __restrict__ W, int ldw, int row_off,
    bf16* __restrict__ Wt, int K, int n_off, int tn, int tk) {
    __shared__ float tile[32][33];
    int n0 = tn * 32, k0 = tk * 32;
    int tx = threadIdx.x, ty = threadIdx.y;  // 32 x 8
#pragma unroll
    for (int i = ty; i < 32; i += 8)
        tile[i][tx] = W[(size_t)(row_off + k0 + i) * ldw + n0 + tx];
    __syncthreads();
#pragma unroll
    for (int i = ty; i < 32; i += 8)
        Wt[(size_t)(n_off + n0 + i) * K + k0 + tx] = __float2bfloat16(tile[tx][i]);
}

// node-side weights: wt_n (Wq top + Wkv top), wt_wo, wt_f1, wt_f2, bias concat
__global__ void k_prep_node(const float* __restrict__ Wq_w,
                            const float* __restrict__ Wq_b,
                            const float* __restrict__ Wkv_w,
                            const float* __restrict__ Wkv_b,
                            const float* __restrict__ Wo_w,
                            const float* __restrict__ f1w,
                            const float* __restrict__ f2w) {
    int id = blockIdx.x;
    if (id < 64) {
        transpose_tile(Wq_w, 256, 0, g_wt_n, 256, 0, id & 7, id >> 3);
    } else if (id < 192) {
        int j = id - 64;
        transpose_tile(Wkv_w, 512, 0, g_wt_n, 256, 256, j % 16, j / 16);
    } else if (id < 256) {
        int j = id - 192;
        transpose_tile(Wo_w, 256, 0, g_wt_wo, 256, 0, j & 7, j >> 3);
    } else if (id < 512) {
        int j = id - 256;
        transpose_tile(f1w, 1024, 0, g_wt_f1, 256, 0, j % 32, j / 32);
    } else if (id < 768) {
        int j = id - 512;
        transpose_tile(f2w, 256, 0, g_wt_f2, 1024, 0, j % 8, j / 8);
    } else {
        int i = (id - 768) * 256 + threadIdx.y * 32 + threadIdx.x;
        if (i < 256) g_bias_n[i] = Wq_b[i];
        else if (i < 768) g_bias_n[i] = Wkv_b[i - 256];
    }
}

// edge-side weights: wt_e (Wq bottom + Wkv bottom)
__global__ void k_prep_edge(const float* __restrict__ Wq_w,
                            const float* __restrict__ Wkv_w) {
    int id = blockIdx.x;
    if (id < 64) {
        transpose_tile(Wq_w, 256, 256, g_wt_e, 256, 0, id & 7, id >> 3);
    } else {
        int j = id - 64;
        transpose_tile(Wkv_w, 512, 256, g_wt_e, 256, 256, j % 16, j / 16);
    }
}

// node misc: cvt h_n -> bf16, zero att dest + denom
__global__ void k_node_misc(const float* __restrict__ h_n, int NN) {
    int i = blockIdx.x * 256 + threadIdx.x;
    int n1 = NN * 64;    // float4 quads of h_n
    if (i < n1) {
        float4 v = *(const float4*)(h_n + 4 * i);
        uint2 p;
        p.x = pack_bf16x2(v.x, v.y);
        p.y = pack_bf16x2(v.z, v.w);
        *(uint2*)(g_hn_bf + 4 * i) = p;
    }
    if (i < NN * 128) ((unsigned*)g_att_bf)[i] = 0u;
    if (i < NN * 4) g_denom[i] = 0.0f;
}

__global__ void k_cvt(const float* __restrict__ x, bf16* __restrict__ y, int n4) {
    int i = blockIdx.x * blockDim.x + threadIdx.x;
    if (i >= n4) return;
    float4 v = *(const float4*)(x + 4 * i);
    uint2 p;
    p.x = pack_bf16x2(v.x, v.y);
    p.y = pack_bf16x2(v.z, v.w);
    *(uint2*)(y + 4 * i) = p;
}

// ---------------- bf16 tensor-core GEMM (4-stage cp.async + ldmatrix) ------
#define RS 80                        // bytes per smem row (64 data + 16 pad)
#define MSTG (128 * RS)              // one matrix stage: 10240 B
#define PSTG (2 * MSTG)              // A+B stage pair: 20480 B
#define NSTAGE 4
#define GSM_BYTES (NSTAGE * PSTG)    // 81920 B dynamic smem

__global__ __launch_bounds__(256)
void tgemm_bf(const bf16* __restrict__ A, int M, int K,
              const bf16* __restrict__ Wt, const float* __restrict__ bias,
              void* __restrict__ C, int N, int act, int obf16) {
    extern __shared__ char dsm[];
    const unsigned base = (unsigned)__cvta_generic_to_shared(dsm);

    const int cb = blockIdx.x * 128;
    const int rb = blockIdx.y * 128;

    const int t    = threadIdx.x;
    const int lane = t & 31;
    const int wid  = t >> 5;
    const int wm   = wid & 1;
    const int wn   = wid >> 1;
    const int g    = lane >> 2;
    const int tg   = lane & 3;

    float acc[4][4][4];
#pragma unroll
    for (int mt = 0; mt < 4; mt++)
#pragma unroll
        for (int nt = 0; nt < 4; nt++)
#pragma unroll
            for (int r = 0; r < 4; r++) acc[mt][nt][r] = 0.0f;

    const int NT = K / 32;
    const int s_row = t >> 1;
    const int s_c   = (t & 1) * 2;

    auto stage = [&](int kt) {
        unsigned sb = base + (kt & (NSTAGE - 1)) * PSTG;
        int k0 = kt * 32;
        int ga = rb + s_row; if (ga >= M) ga = M - 1;
#pragma unroll
        for (int cc = 0; cc < 2; cc++) {
            int c = s_c + cc;
            cpa16(sb + s_row * RS + c * 16, A + (size_t)ga * K + k0 + c * 8);
            cpa16(sb + MSTG + s_row * RS + c * 16,
                  Wt + (size_t)(cb + s_row) * K + k0 + c * 8);
        }
        cpa_commit();
    };

    stage(0);
    if (NT > 1) stage(1); else cpa_commit();
    if (NT > 2) stage(2); else cpa_commit();

    const unsigned aOff = (lane & 15) * RS + (lane >> 4) * 16;
    const unsigned bOff = (lane & 7) * RS + ((lane >> 3) & 1) * 16;

    for (int kt = 0; kt < NT; kt++) {
        cpa_wait<2>();
        __syncthreads();
        if (kt + 3 < NT) stage(kt + 3); else cpa_commit();

        const unsigned aB = base + (kt & (NSTAGE - 1)) * PSTG;
        const unsigned bB = aB + MSTG;
#pragma unroll
        for (int ko = 0; ko < 2; ko++) {
            unsigned a[4][4], b[4][2];
#pragma unroll
            for (int mt = 0; mt < 4; mt++)
                ldm_x4(a[mt], aB + (wm * 64 + mt * 16) * RS + aOff + ko * 32);
#pragma unroll
            for (int nt = 0; nt < 4; nt++)
                ldm_x2(b[nt], bB + (wn * 32 + nt * 8) * RS + bOff + ko * 32);
#pragma unroll
            for (int mt = 0; mt < 4; mt++)
#pragma unroll
                for (int nt = 0; nt < 4; nt++)
                    mma_bf16(acc[mt][nt], a[mt], b[nt]);
        }
    }

#pragma unroll
    for (int mt = 0; mt < 4; mt++) {
        int r0 = rb + wm * 64 + mt * 16 + g;
#pragma unroll
        for (int nt = 0; nt < 4; nt++) {
            int lcol = wn * 32 + nt * 8 + tg * 2;
            int ccol = cb + lcol;
            float v0 = acc[mt][nt][0], v1 = acc[mt][nt][1];
            float v2 = acc[mt][nt][2], v3 = acc[mt][nt][3];
            if (bias) {
                float bb0 = bias[lcol], bb1 = bias[lcol + 1];
                v0 += bb0; v1 += bb1; v2 += bb0; v3 += bb1;
            }
            if (act == 1) {
                v0 = gelu_exact(v0); v1 = gelu_exact(v1);
                v2 = gelu_exact(v2); v3 = gelu_exact(v3);
            }
            if (obf16) {
                bf16* Cb = (bf16*)C;
                if (r0 < M)
                    *(unsigned*)(Cb + (size_t)r0 * N + ccol) = pack_bf16x2(v0, v1);
                if (r0 + 8 < M)
                    *(unsigned*)(Cb + (size_t)(r0 + 8) * N + ccol) = pack_bf16x2(v2, v3);
            } else {
                float* Cf = (float*)C;
                if (r0 < M) {
                    Cf[(size_t)r0 * N + ccol]     = v0;
                    Cf[(size_t)r0 * N + ccol + 1] = v1;
                }
                if (r0 + 8 < M) {
                    Cf[(size_t)(r0 + 8) * N + ccol]     = v2;
                    Cf[(size_t)(r0 + 8) * N + ccol + 1] = v3;
                }
            }
        }
    }
}

// ------- per-edge scores + exp + segment-sum (max-free: |s| <~ 2) ---------
__device__ __forceinline__ float dot8add(uint4 qa, uint4 qb, uint4 ka, uint4 kb) {
    float s = 0.f;
    const __nv_bfloat162* q1 = (const __nv_bfloat162*)&qa;
    const __nv_bfloat162* q2 = (const __nv_bfloat162*)&qb;
    const __nv_bfloat162* k1 = (const __nv_bfloat162*)&ka;
    const __nv_bfloat162* k2 = (const __nv_bfloat162*)&kb;
#pragma unroll
    for (int j = 0; j < 4; j++) {
        float2 x1 = __bfloat1622float2(q1[j]);
        float2 x2 = __bfloat1622float2(q2[j]);
        float2 y1 = __bfloat1622float2(k1[j]);
        float2 y2 = __bfloat1622float2(k2[j]);
        s += (x1.x + x2.x) * (y1.x + y2.x) + (x1.y + x2.y) * (y1.y + y2.y);
    }
    return s;
}

__global__ void k_scores(const int* __restrict__ ei, int NE) {
    int w = (blockIdx.x * blockDim.x + threadIdx.x) >> 5;
    int lane = threadIdx.x & 31;
    if (w >= NE) return;
    int src = ei[w];
    int dst = ei[NE + w];
    const bf16* qn = g_node_projh + (size_t)src * 768;
    const bf16* kn = g_node_projh + (size_t)dst * 768 + 256;
    const bf16* qe = g_edge_projh + (size_t)w * 768;
    const bf16* ke = qe + 256;
    uint4 a = *(const uint4*)(qn + lane * 8);
    uint4 b = *(const uint4*)(qe + lane * 8);
    uint4 c = *(const uint4*)(kn + lane * 8);
    uint4 d = *(const uint4*)(ke + lane * 8);
    float s = dot8add(a, b, c, d);
#pragma unroll
    for (int off = 1; off < 8; off <<= 1)
        s += __shfl_xor_sync(0xffffffffu, s, off);
    if ((lane & 7) == 0) {
        int h = lane >> 3;
        float ex = expf(s * 0.125f);   // 1/sqrt(64); scores O(1), no max needed
        g_scores[(size_t)w * 4 + h] = ex;
        atomicAdd(&g_denom[src * 4 + h], ex);
    }
}

// ---------------- attn * V scatter (bf16x2 atomics) ------------------------
__global__ void k_scatter(const int* __restrict__ ei, int NE) {
    int w = (blockIdx.x * blockDim.x + threadIdx.x) >> 5;
    int lane = threadIdx.x & 31;
    if (w >= NE) return;
    int src = ei[w];
    int dst = ei[NE + w];
    int h = lane >> 3;
    float aw = g_scores[(size_t)w * 4 + h] / g_denom[src * 4 + h];
    const bf16* vn = g_node_projh + (size_t)dst * 768 + 512;
    const bf16* ve = g_edge_projh + (size_t)w * 768 + 512;
    uint4 a = *(const uint4*)(vn + lane * 8);
    uint4 b = *(const uint4*)(ve + lane * 8);
    __nv_bfloat162* o = (__nv_bfloat162*)(g_att_bf + (size_t)src * 256 + lane * 8);
    const __nv_bfloat162* v1 = (const __nv_bfloat162*)&a;
    const __nv_bfloat162* v2 = (const __nv_bfloat162*)&b;
#pragma unroll
    for (int j = 0; j < 4; j++) {
        float2 x1 = __bfloat1622float2(v1[j]);
        float2 x2 = __bfloat1622float2(v2[j]);
        __nv_bfloat162 add = __float22bfloat162_rn(
            make_float2(aw * (x1.x + x2.x), aw * (x1.y + x2.y)));
        atomicAdd(o + j, add);
    }
}

// ------------- layernorm (warp per row of 256), optional bf16 copy --------
__global__ void k_ln(const float* __restrict__ x, const float* __restrict__ res,
                     const float* __restrict__ g, const float* __restrict__ b,
                     float* __restrict__ out, bf16* __restrict__ out_bf, int M) {
    int w = (blockIdx.x * blockDim.x + threadIdx.x) >> 5;
    int lane = threadIdx.x & 31;
    if (w >= M) return;
    float v[8];
    float s = 0.f;
#pragma unroll
    for (int j = 0; j < 8; j++) {
        int i = lane + 32 * j;
        v[j] = x[(size_t)w * 256 + i] + res[(size_t)w * 256 + i];
        s += v[j];
    }
#pragma unroll
    for (int off = 16; off; off >>= 1) s += __shfl_xor_sync(0xffffffffu, s, off);
    float mu = s * (1.0f / 256.0f);
    float q = 0.f;
#pragma unroll
    for (int j = 0; j < 8; j++) { float d = v[j] - mu; q += d * d; }
#pragma unroll
    for (int off = 16; off; off >>= 1) q += __shfl_xor_sync(0xffffffffu, q, off);
    float rstd = rsqrtf(q * (1.0f / 256.0f) + 1e-5f);
#pragma unroll
    for (int j = 0; j < 8; j++) {
        int i = lane + 32 * j;
        float y = (v[j] - mu) * rstd * g[i] + b[i];
        out[(size_t)w * 256 + i] = y;
        if (out_bf) out_bf[(size_t)w * 256 + i] = __float2bfloat16(y);
    }
}

// ---------------- host launch ----------------------------------------------
extern "C" void kernel_launch(void* const* d_in, const int* in_sizes, int n_in,
                              void* d_out, int out_size) {
    const float* h_n   = (const float*)d_in[0];
    const float* h_e   = (const float*)d_in[1];
    const int*   ei    = (const int*)d_in[2];   // int32 (JAX x64 disabled)
    const float* Wq_w  = (const float*)d_in[3];
    const float* Wq_b  = (const float*)d_in[4];
    const float* Wkv_w = (const float*)d_in[5];
    const float* Wkv_b = (const float*)d_in[6];
    const float* Wo_w  = (const float*)d_in[7];
    const float* Wo_b  = (const float*)d_in[8];
    const float* ln1_g = (const float*)d_in[9];
    const float* ln1_b = (const float*)d_in[10];
    const float* f1w   = (const float*)d_in[11];
    const float* f1b   = (const float*)d_in[12];
    const float* f2w   = (const float*)d_in[13];
    const float* f2b   = (const float*)d_in[14];
    const float* ln2_g = (const float*)d_in[15];
    const float* ln2_b = (const float*)d_in[16];
    float* out = (float*)d_out;

    int NN = in_sizes[0] / DIM;
    int NE = in_sizes[1] / DIM;

    static int inited = 0;
    static cudaStream_t s2;
    static cudaEvent_t evFork, evJoin;
    if (!inited) {
        cudaFuncSetAttribute(tgemm_bf,
                             cudaFuncAttributeMaxDynamicSharedMemorySize,
                             GSM_BYTES);
        cudaStreamCreateWithFlags(&s2, cudaStreamNonBlocking);
        cudaEventCreateWithFlags(&evFork, cudaEventDisableTiming);
        cudaEventCreateWithFlags(&evJoin, cudaEventDisableTiming);
        inited = 1;
    }

    void *p_hn, *p_he, *p_nph, *p_eph, *p_attb, *p_tmp;
    void *p_h1, *p_h1b, *p_ffb, *p_ff2;
    void *p_wtn, *p_wte, *p_wtwo, *p_wtf1, *p_wtf2, *p_bn;
    cudaGetSymbolAddress(&p_hn, g_hn_bf);
    cudaGetSymbolAddress(&p_he, g_he_bf);
    cudaGetSymbolAddress(&p_nph, g_node_projh);
    cudaGetSymbolAddress(&p_eph, g_edge_projh);
    cudaGetSymbolAddress(&p_attb, g_att_bf);
    cudaGetSymbolAddress(&p_tmp, g_tmp);
    cudaGetSymbolAddress(&p_h1, g_h1);
    cudaGetSymbolAddress(&p_h1b, g_h1_bf);
    cudaGetSymbolAddress(&p_ffb, g_ff_bf);
    cudaGetSymbolAddress(&p_ff2, g_ff2);
    cudaGetSymbolAddress(&p_wtn, g_wt_n);
    cudaGetSymbolAddress(&p_wte, g_wt_e);
    cudaGetSymbolAddress(&p_wtwo, g_wt_wo);
    cudaGetSymbolAddress(&p_wtf1, g_wt_f1);
    cudaGetSymbolAddress(&p_wtf2, g_wt_f2);
    cudaGetSymbolAddress(&p_bn, g_bias_n);

    dim3 tb(32, 8);

    // ---- fork: node-side branch on s2 ----
    cudaEventRecord(evFork, 0);
    cudaStreamWaitEvent(s2, evFork, 0);

    k_prep_node<<<771, tb, 0, s2>>>(Wq_w, Wq_b, Wkv_w, Wkv_b, Wo_w, f1w, f2w);
    k_node_misc<<<(NN * 128 + 255) / 256, 256, 0, s2>>>(h_n, NN);
    tgemm_bf<<<dim3(6, (NN + 127) / 128), 256, GSM_BYTES, s2>>>(
        (const bf16*)p_hn, NN, 256, (const bf16*)p_wtn, (const float*)p_bn,
        p_nph, 768, 0, 1);
    cudaEventRecord(evJoin, s2);

    // ---- edge-side branch on stream 0 (critical path) ----
    k_prep_edge<<<192, tb>>>(Wq_w, Wkv_w);
    k_cvt<<<(NE * 64 + 255) / 256, 256>>>(h_e, (bf16*)p_he, NE * 64);
    tgemm_bf<<<dim3(6, (NE + 127) / 128), 256, GSM_BYTES>>>(
        (const bf16*)p_he, NE, 256, (const bf16*)p_wte, nullptr, p_eph, 768, 0, 1);

    // ---- join ----
    cudaStreamWaitEvent(0, evJoin, 0);

    // 4. per-edge scores + exp + segment sum
    k_scores<<<(NE + 7) / 8, 256>>>(ei, NE);

    // 5. attn-weighted V scatter (bf16x2 atomics into g_att_bf)
    k_scatter<<<(NE + 7) / 8, 256>>>(ei, NE);

    // 6. output projection Wo (fp32 out)
    tgemm_bf<<<dim3(2, (NN + 127) / 128), 256, GSM_BYTES>>>(
        (const bf16*)p_attb, NN, 256, (const bf16*)p_wtwo, Wo_b, p_tmp, 256, 0, 0);

    // 7. LN1(h_n + attn_proj) -> fp32 + bf16
    k_ln<<<(NN + 7) / 8, 256>>>(h_n, (const float*)p_tmp, ln1_g, ln1_b,
                                (float*)p_h1, (bf16*)p_h1b, NN);

    // 8. FFN1 + exact GELU -> bf16
    tgemm_bf<<<dim3(8, (NN + 127) / 128), 256, GSM_BYTES>>>(
        (const bf16*)p_h1b, NN, 256, (const bf16*)p_wtf1, f1b, p_ffb, 1024, 1, 1);

    // 9. FFN2 (fp32 out, K=1024)
    tgemm_bf<<<dim3(2, (NN + 127) / 128), 256, GSM_BYTES>>>(
        (const bf16*)p_ffb, NN, 1024, (const bf16*)p_wtf2, f2b, p_ff2, 256, 0, 0);

    // 10. LN2(h1 + ff) -> output
    k_ln<<<(NN + 7) / 8, 256>>>((const float*)p_h1, (const float*)p_ff2,
                                ln2_g, ln2_b, out, nullptr, NN);
}

// round 15
// speedup vs baseline: 1.5641x; 1.0112x over previous
#include <cuda_runtime.h>
#include <cuda_bf16.h>
#include <math.h>
#include <stdint.h>

// Problem constants
#define NN_MAX 50000
#define NE_MAX 400000
#define DIM 256
#define NHEAD 4

typedef __nv_bfloat16 bf16;

// ---------------- scratch (static __device__ arrays, no allocation) -------
__device__ bf16     g_hn_bf[NN_MAX * 256];       // h_n bf16
__device__ bf16     g_he_bf[NE_MAX * 256];       // h_e bf16
__device__ bf16     g_node_projh[NN_MAX * 768];  // [q|k|v] per node
__device__ bf16     g_edge_projh[NE_MAX * 768];  // [q|k|v] per edge
__device__ float    g_denom[NN_MAX * NHEAD];     // segment sum of exp
__device__ bf16     g_att_bf[NN_MAX * DIM];      // bf16 scatter dest (feeds Wo)
__device__ float    g_tmp[NN_MAX * DIM];         // after Wo
__device__ float    g_h1[NN_MAX * DIM];          // after LN1 (fp32)
__device__ bf16     g_h1_bf[NN_MAX * DIM];       // after LN1 (bf16)
__device__ bf16     g_ff_bf[NN_MAX * 1024];      // after FFN1+gelu (bf16)
__device__ float    g_ff2[NN_MAX * DIM];         // after FFN2
// transposed weights [N][K] K-major, bf16 (built per launch)
__device__ bf16     g_wt_n[768 * 256];
__device__ bf16     g_wt_e[768 * 256];
__device__ bf16     g_wt_wo[256 * 256];
__device__ bf16     g_wt_f1[1024 * 256];
__device__ bf16     g_wt_f2[256 * 1024];
__device__ float    g_bias_n[768];

// ---------------- helpers --------------------------------------------------
__device__ __forceinline__ float gelu_exact(float x) {
    return 0.5f * x * (1.0f + erff(x * 0.70710678118654752440f));
}
__device__ __forceinline__ unsigned pack_bf16x2(float x, float y) {
    __nv_bfloat162 h = __float22bfloat162_rn(make_float2(x, y));
    return reinterpret_cast<unsigned&>(h);
}
__device__ __forceinline__ void mma_bf16(float* c, const unsigned* a,
                                         const unsigned* b) {
    asm volatile(
        "mma.sync.aligned.m16n8k16.row.col.f32.bf16.bf16.f32 "
        "{%0,%1,%2,%3}, {%4,%5,%6,%7}, {%8,%9}, {%0,%1,%2,%3};"
        : "+f"(c[0]), "+f"(c[1]), "+f"(c[2]), "+f"(c[3])
        : "r"(a[0]), "r"(a[1]), "r"(a[2]), "r"(a[3]),
          "r"(b[0]), "r"(b[1]));
}
__device__ __forceinline__ void ldm_x4(unsigned* r, unsigned addr) {
    asm volatile("ldmatrix.sync.aligned.m8n8.x4.shared.b16 {%0,%1,%2,%3}, [%4];"
                 : "=r"(r[0]), "=r"(r[1]), "=r"(r[2]), "=r"(r[3]) : "r"(addr));
}
__device__ __forceinline__ void cpa16(unsigned s, const void* g) {
    asm volatile("cp.async.ca.shared.global [%0], [%1], 16;"
                 :: "r"(s), "l"(g));
}
__device__ __forceinline__ void cpa_commit() {
    asm volatile("cp.async.commit_group;");
}
template <int N>
__device__ __forceinline__ void cpa_wait() {
    asm volatile("cp.async.wait_group %0;" :: "n"(N));
}

// ---------------- fused prologue kernels -----------------------------------
__device__ __forceinline__ void transpose_tile(
    const float* __restrict__ W, int ldw, int row_off,
    bf16* __restrict__ Wt, int K, int n_off, int tn, int tk) {
    __shared__ float tile[32][33];
    int n0 = tn * 32, k0 = tk * 32;
    int tx = threadIdx.x, ty = threadIdx.y;  // 32 x 8
#pragma unroll
    for (int i = ty; i < 32; i += 8)
        tile[i][tx] = W[(size_t)(row_off + k0 + i) * ldw + n0 + tx];
    __syncthreads();
#pragma unroll
    for (int i = ty; i < 32; i += 8)
        Wt[(size_t)(n_off + n0 + i) * K + k0 + tx] = __float2bfloat16(tile[tx][i]);
}

__global__ void k_prep_node(const float* __restrict__ Wq_w,
                            const float* __restrict__ Wq_b,
                            const float* __restrict__ Wkv_w,
                            const float* __restrict__ Wkv_b,
                            const float* __restrict__ Wo_w,
                            const float* __restrict__ f1w,
                            const float* __restrict__ f2w) {
    int id = blockIdx.x;
    if (id < 64) {
        transpose_tile(Wq_w, 256, 0, g_wt_n, 256, 0, id & 7, id >> 3);
    } else if (id < 192) {
        int j = id - 64;
        transpose_tile(Wkv_w, 512, 0, g_wt_n, 256, 256, j % 16, j / 16);
    } else if (id < 256) {
        int j = id - 192;
        transpose_tile(Wo_w, 256, 0, g_wt_wo, 256, 0, j & 7, j >> 3);
    } else if (id < 512) {
        int j = id - 256;
        transpose_tile(f1w, 1024, 0, g_wt_f1, 256, 0, j % 32, j / 32);
    } else if (id < 768) {
        int j = id - 512;
        transpose_tile(f2w, 256, 0, g_wt_f2, 1024, 0, j % 8, j / 8);
    } else {
        int i = (id - 768) * 256 + threadIdx.y * 32 + threadIdx.x;
        if (i < 256) g_bias_n[i] = Wq_b[i];
        else if (i < 768) g_bias_n[i] = Wkv_b[i - 256];
    }
}

__global__ void k_prep_edge(const float* __restrict__ Wq_w,
                            const float* __restrict__ Wkv_w) {
    int id = blockIdx.x;
    if (id < 64) {
        transpose_tile(Wq_w, 256, 256, g_wt_e, 256, 0, id & 7, id >> 3);
    } else {
        int j = id - 64;
        transpose_tile(Wkv_w, 512, 256, g_wt_e, 256, 256, j % 16, j / 16);
    }
}

// node misc: cvt h_n -> bf16, zero att dest + denom
__global__ void k_node_misc(const float* __restrict__ h_n, int NN) {
    int i = blockIdx.x * 256 + threadIdx.x;
    int n1 = NN * 64;    // float4 quads of h_n
    if (i < n1) {
        float4 v = *(const float4*)(h_n + 4 * i);
        uint2 p;
        p.x = pack_bf16x2(v.x, v.y);
        p.y = pack_bf16x2(v.z, v.w);
        *(uint2*)(g_hn_bf + 4 * i) = p;
    }
    if (i < NN * 128) ((unsigned*)g_att_bf)[i] = 0u;
    if (i < NN * 4) g_denom[i] = 0.0f;
}

__global__ void k_cvt(const float* __restrict__ x, bf16* __restrict__ y, int n4) {
    int i = blockIdx.x * blockDim.x + threadIdx.x;
    if (i >= n4) return;
    float4 v = *(const float4*)(x + 4 * i);
    uint2 p;
    p.x = pack_bf16x2(v.x, v.y);
    p.y = pack_bf16x2(v.z, v.w);
    *(uint2*)(y + 4 * i) = p;
}

// ---------------- bf16 tensor-core GEMM (4-stage cp.async + ldmatrix) ------
#define RS 80                        // bytes per smem row (64 data + 16 pad)
#define MSTG (128 * RS)              // one matrix stage: 10240 B
#define PSTG (2 * MSTG)              // A+B stage pair: 20480 B
#define NSTAGE 4
#define GSM_BYTES (NSTAGE * PSTG)    // 81920 B dynamic smem

__global__ __launch_bounds__(256)
void tgemm_bf(const bf16* __restrict__ A, int M, int K,
              const bf16* __restrict__ Wt, const float* __restrict__ bias,
              void* __restrict__ C, int N, int act, int obf16) {
    extern __shared__ char dsm[];
    const unsigned base = (unsigned)__cvta_generic_to_shared(dsm);

    const int cb = blockIdx.x * 128;
    const int rb = blockIdx.y * 128;

    const int t    = threadIdx.x;
    const int lane = t & 31;
    const int wid  = t >> 5;
    const int wm   = wid & 1;
    const int wn   = wid >> 1;
    const int g    = lane >> 2;
    const int tg   = lane & 3;

    float acc[4][4][4];
#pragma unroll
    for (int mt = 0; mt < 4; mt++)
#pragma unroll
        for (int nt = 0; nt < 4; nt++)
#pragma unroll
            for (int r = 0; r < 4; r++) acc[mt][nt][r] = 0.0f;

    const int NT = K / 32;
    const int s_row = t >> 1;
    const int s_c   = (t & 1) * 2;

    auto stage = [&](int kt) {
        unsigned sb = base + (kt & (NSTAGE - 1)) * PSTG;
        int k0 = kt * 32;
        int ga = rb + s_row; if (ga >= M) ga = M - 1;
#pragma unroll
        for (int cc = 0; cc < 2; cc++) {
            int c = s_c + cc;
            cpa16(sb + s_row * RS + c * 16, A + (size_t)ga * K + k0 + c * 8);
            cpa16(sb + MSTG + s_row * RS + c * 16,
                  Wt + (size_t)(cb + s_row) * K + k0 + c * 8);
        }
        cpa_commit();
    };

    stage(0);
    if (NT > 1) stage(1); else cpa_commit();
    if (NT > 2) stage(2); else cpa_commit();

    // A: x4 per (mt, ko): lanes 0-15 rows, 16-31 second 16B half
    const unsigned aOff = (lane & 15) * RS + (lane >> 4) * 16;
    // B paired x4: matrices = (nt, k0-7), (nt, k8-15), (nt+1, k0-7), (nt+1, k8-15)
    const unsigned bOff4 = (lane & 7) * RS + ((lane >> 3) & 1) * 16
                         + (lane >> 4) * 8 * RS;

    for (int kt = 0; kt < NT; kt++) {
        cpa_wait<2>();
        __syncthreads();
        if (kt + 3 < NT) stage(kt + 3); else cpa_commit();

        const unsigned aB = base + (kt & (NSTAGE - 1)) * PSTG;
        const unsigned bB = aB + MSTG;
#pragma unroll
        for (int ko = 0; ko < 2; ko++) {
            unsigned a[4][4], b[4][2];
#pragma unroll
            for (int mt = 0; mt < 4; mt++)
                ldm_x4(a[mt], aB + (wm * 64 + mt * 16) * RS + aOff + ko * 32);
#pragma unroll
            for (int p = 0; p < 2; p++) {
                unsigned r4[4];
                ldm_x4(r4, bB + (wn * 32 + p * 16) * RS + bOff4 + ko * 32);
                b[2 * p][0] = r4[0]; b[2 * p][1] = r4[1];
                b[2 * p + 1][0] = r4[2]; b[2 * p + 1][1] = r4[3];
            }
#pragma unroll
            for (int mt = 0; mt < 4; mt++)
#pragma unroll
                for (int nt = 0; nt < 4; nt++)
                    mma_bf16(acc[mt][nt], a[mt], b[nt]);
        }
    }

#pragma unroll
    for (int mt = 0; mt < 4; mt++) {
        int r0 = rb + wm * 64 + mt * 16 + g;
#pragma unroll
        for (int nt = 0; nt < 4; nt++) {
            int lcol = wn * 32 + nt * 8 + tg * 2;
            int ccol = cb + lcol;
            float v0 = acc[mt][nt][0], v1 = acc[mt][nt][1];
            float v2 = acc[mt][nt][2], v3 = acc[mt][nt][3];
            if (bias) {
                float bb0 = bias[lcol], bb1 = bias[lcol + 1];
                v0 += bb0; v1 += bb1; v2 += bb0; v3 += bb1;
            }
            if (act == 1) {
                v0 = gelu_exact(v0); v1 = gelu_exact(v1);
                v2 = gelu_exact(v2); v3 = gelu_exact(v3);
            }
            if (obf16) {
                bf16* Cb = (bf16*)C;
                if (r0 < M)
                    *(unsigned*)(Cb + (size_t)r0 * N + ccol) = pack_bf16x2(v0, v1);
                if (r0 + 8 < M)
                    *(unsigned*)(Cb + (size_t)(r0 + 8) * N + ccol) = pack_bf16x2(v2, v3);
            } else {
                float* Cf = (float*)C;
                if (r0 < M) {
                    Cf[(size_t)r0 * N + ccol]     = v0;
                    Cf[(size_t)r0 * N + ccol + 1] = v1;
                }
                if (r0 + 8 < M) {
                    Cf[(size_t)(r0 + 8) * N + ccol]     = v2;
                    Cf[(size_t)(r0 + 8) * N + ccol + 1] = v3;
                }
            }
        }
    }
}

// ------- fused edge attention: score + exp + denom + UNNORMALIZED scatter --
// Normalization deferred to k_norm (out = accum/denom is per-(node,head)).
__global__ void k_edge_attn(const int* __restrict__ ei, int NE) {
    int w = (blockIdx.x * blockDim.x + threadIdx.x) >> 5;
    int lane = threadIdx.x & 31;
    if (w >= NE) return;
    int src = ei[w];
    int dst = ei[NE + w];
    const bf16* qn = g_node_projh + (size_t)src * 768;
    const bf16* kn = g_node_projh + (size_t)dst * 768 + 256;
    const bf16* vn = g_node_projh + (size_t)dst * 768 + 512;
    const bf16* qe = g_edge_projh + (size_t)w * 768;
    const bf16* ke = qe + 256;
    const bf16* ve = qe + 512;

    uint4 a = *(const uint4*)(qn + lane * 8);
    uint4 b = *(const uint4*)(qe + lane * 8);
    uint4 c = *(const uint4*)(kn + lane * 8);
    uint4 d = *(const uint4*)(ke + lane * 8);

    float s = 0.f;
    {
        const __nv_bfloat162* q1 = (const __nv_bfloat162*)&a;
        const __nv_bfloat162* q2 = (const __nv_bfloat162*)&b;
        const __nv_bfloat162* k1 = (const __nv_bfloat162*)&c;
        const __nv_bfloat162* k2 = (const __nv_bfloat162*)&d;
#pragma unroll
        for (int j = 0; j < 4; j++) {
            float2 x1 = __bfloat1622float2(q1[j]);
            float2 x2 = __bfloat1622float2(q2[j]);
            float2 y1 = __bfloat1622float2(k1[j]);
            float2 y2 = __bfloat1622float2(k2[j]);
            s += (x1.x + x2.x) * (y1.x + y2.x) + (x1.y + x2.y) * (y1.y + y2.y);
        }
    }
    // butterfly over the 8-lane head group: all lanes get the head's sum
#pragma unroll
    for (int off = 1; off < 8; off <<= 1)
        s += __shfl_xor_sync(0xffffffffu, s, off);

    float ex = expf(s * 0.125f);   // 1/sqrt(64); scores O(1), no max needed
    int h = lane >> 3;
    if ((lane & 7) == 0)
        atomicAdd(&g_denom[src * 4 + h], ex);

    uint4 va = *(const uint4*)(vn + lane * 8);
    uint4 vb = *(const uint4*)(ve + lane * 8);
    __nv_bfloat162* o = (__nv_bfloat162*)(g_att_bf + (size_t)src * 256 + lane * 8);
    const __nv_bfloat162* v1 = (const __nv_bfloat162*)&va;
    const __nv_bfloat162* v2 = (const __nv_bfloat162*)&vb;
#pragma unroll
    for (int j = 0; j < 4; j++) {
        float2 x1 = __bfloat1622float2(v1[j]);
        float2 x2 = __bfloat1622float2(v2[j]);
        __nv_bfloat162 add = __float22bfloat162_rn(
            make_float2(ex * (x1.x + x2.x), ex * (x1.y + x2.y)));
        atomicAdd(o + j, add);
    }
}

// ------- normalize attn accum by denom (in place, bf16) --------------------
// Guard denom==0 (isolated nodes): reference gives 0 there (empty segment_sum).
__global__ void k_norm(int NN) {
    int i = blockIdx.x * blockDim.x + threadIdx.x;   // bf16x2 word index
    if (i >= NN * 128) return;
    int node = i >> 7;
    int h = (i & 127) >> 5;                          // 32 words per head
    float d = g_denom[node * 4 + h];
    float inv = (d > 0.0f) ? (1.0f / d) : 0.0f;
    __nv_bfloat162* p = (__nv_bfloat162*)g_att_bf + i;
    float2 v = __bfloat1622float2(*p);
    *p = __float22bfloat162_rn(make_float2(v.x * inv, v.y * inv));
}

// ------------- layernorm (warp per row of 256), optional bf16 copy --------
__global__ void k_ln(const float* __restrict__ x, const float* __restrict__ res,
                     const float* __restrict__ g, const float* __restrict__ b,
                     float* __restrict__ out, bf16* __restrict__ out_bf, int M) {
    int w = (blockIdx.x * blockDim.x + threadIdx.x) >> 5;
    int lane = threadIdx.x & 31;
    if (w >= M) return;
    float v[8];
    float s = 0.f;
#pragma unroll
    for (int j = 0; j < 8; j++) {
        int i = lane + 32 * j;
        v[j] = x[(size_t)w * 256 + i] + res[(size_t)w * 256 + i];
        s += v[j];
    }
#pragma unroll
    for (int off = 16; off; off >>= 1) s += __shfl_xor_sync(0xffffffffu, s, off);
    float mu = s * (1.0f / 256.0f);
    float q = 0.f;
#pragma unroll
    for (int j = 0; j < 8; j++) { float d = v[j] - mu; q += d * d; }
#pragma unroll
    for (int off = 16; off; off >>= 1) q += __shfl_xor_sync(0xffffffffu, q, off);
    float rstd = rsqrtf(q * (1.0f / 256.0f) + 1e-5f);
#pragma unroll
    for (int j = 0; j < 8; j++) {
        int i = lane + 32 * j;
        float y = (v[j] - mu) * rstd * g[i] + b[i];
        out[(size_t)w * 256 + i] = y;
        if (out_bf) out_bf[(size_t)w * 256 + i] = __float2bfloat16(y);
    }
}

// ---------------- host launch ----------------------------------------------
extern "C" void kernel_launch(void* const* d_in, const int* in_sizes, int n_in,
                              void* d_out, int out_size) {
    const float* h_n   = (const float*)d_in[0];
    const float* h_e   = (const float*)d_in[1];
    const int*   ei    = (const int*)d_in[2];   // int32 (JAX x64 disabled)
    const float* Wq_w  = (const float*)d_in[3];
    const float* Wq_b  = (const float*)d_in[4];
    const float* Wkv_w = (const float*)d_in[5];
    const float* Wkv_b = (const float*)d_in[6];
    const float* Wo_w  = (const float*)d_in[7];
    const float* Wo_b  = (const float*)d_in[8];
    const float* ln1_g = (const float*)d_in[9];
    const float* ln1_b = (const float*)d_in[10];
    const float* f1w   = (const float*)d_in[11];
    const float* f1b   = (const float*)d_in[12];
    const float* f2w   = (const float*)d_in[13];
    const float* f2b   = (const float*)d_in[14];
    const float* ln2_g = (const float*)d_in[15];
    const float* ln2_b = (const float*)d_in[16];
    float* out = (float*)d_out;

    int NN = in_sizes[0] / DIM;
    int NE = in_sizes[1] / DIM;

    static int inited = 0;
    static cudaStream_t s2;
    static cudaEvent_t evFork, evJoin;
    if (!inited) {
        cudaFuncSetAttribute(tgemm_bf,
                             cudaFuncAttributeMaxDynamicSharedMemorySize,
                             GSM_BYTES);
        cudaStreamCreateWithFlags(&s2, cudaStreamNonBlocking);
        cudaEventCreateWithFlags(&evFork, cudaEventDisableTiming);
        cudaEventCreateWithFlags(&evJoin, cudaEventDisableTiming);
        inited = 1;
    }

    void *p_hn, *p_he, *p_nph, *p_eph, *p_attb, *p_tmp;
    void *p_h1, *p_h1b, *p_ffb, *p_ff2;
    void *p_wtn, *p_wte, *p_wtwo, *p_wtf1, *p_wtf2, *p_bn;
    cudaGetSymbolAddress(&p_hn, g_hn_bf);
    cudaGetSymbolAddress(&p_he, g_he_bf);
    cudaGetSymbolAddress(&p_nph, g_node_projh);
    cudaGetSymbolAddress(&p_eph, g_edge_projh);
    cudaGetSymbolAddress(&p_attb, g_att_bf);
    cudaGetSymbolAddress(&p_tmp, g_tmp);
    cudaGetSymbolAddress(&p_h1, g_h1);
    cudaGetSymbolAddress(&p_h1b, g_h1_bf);
    cudaGetSymbolAddress(&p_ffb, g_ff_bf);
    cudaGetSymbolAddress(&p_ff2, g_ff2);
    cudaGetSymbolAddress(&p_wtn, g_wt_n);
    cudaGetSymbolAddress(&p_wte, g_wt_e);
    cudaGetSymbolAddress(&p_wtwo, g_wt_wo);
    cudaGetSymbolAddress(&p_wtf1, g_wt_f1);
    cudaGetSymbolAddress(&p_wtf2, g_wt_f2);
    cudaGetSymbolAddress(&p_bn, g_bias_n);

    dim3 tb(32, 8);

    // ---- fork: node-side branch on s2 ----
    cudaEventRecord(evFork, 0);
    cudaStreamWaitEvent(s2, evFork, 0);

    k_prep_node<<<771, tb, 0, s2>>>(Wq_w, Wq_b, Wkv_w, Wkv_b, Wo_w, f1w, f2w);
    k_node_misc<<<(NN * 128 + 255) / 256, 256, 0, s2>>>(h_n, NN);
    tgemm_bf<<<dim3(6, (NN + 127) / 128), 256, GSM_BYTES, s2>>>(
        (const bf16*)p_hn, NN, 256, (const bf16*)p_wtn, (const float*)p_bn,
        p_nph, 768, 0, 1);
    cudaEventRecord(evJoin, s2);

    // ---- edge-side branch on stream 0 (critical path) ----
    k_prep_edge<<<192, tb>>>(Wq_w, Wkv_w);
    k_cvt<<<(NE * 64 + 255) / 256, 256>>>(h_e, (bf16*)p_he, NE * 64);
    tgemm_bf<<<dim3(6, (NE + 127) / 128), 256, GSM_BYTES>>>(
        (const bf16*)p_he, NE, 256, (const bf16*)p_wte, nullptr, p_eph, 768, 0, 1);

    // ---- join ----
    cudaStreamWaitEvent(0, evJoin, 0);

    // 4. fused edge attention (scores + exp + denom + unnormalized scatter)
    k_edge_attn<<<(NE + 7) / 8, 256>>>(ei, NE);

    // 5. normalize by denom (in place, guarded)
    k_norm<<<(NN * 128 + 255) / 256, 256>>>(NN);

    // 6. output projection Wo (fp32 out)
    tgemm_bf<<<dim3(2, (NN + 127) / 128), 256, GSM_BYTES>>>(
        (const bf16*)p_attb, NN, 256, (const bf16*)p_wtwo, Wo_b, p_tmp, 256, 0, 0);

    // 7. LN1(h_n + attn_proj) -> fp32 + bf16
    k_ln<<<(NN + 7) / 8, 256>>>(h_n, (const float*)p_tmp, ln1_g, ln1_b,
                                (float*)p_h1, (bf16*)p_h1b, NN);

    // 8. FFN1 + exact GELU -> bf16
    tgemm_bf<<<dim3(8, (NN + 127) / 128), 256, GSM_BYTES>>>(
        (const bf16*)p_h1b, NN, 256, (const bf16*)p_wtf1, f1b, p_ffb, 1024, 1, 1);

    // 9. FFN2 (fp32 out, K=1024)
    tgemm_bf<<<dim3(2, (NN + 127) / 128), 256, GSM_BYTES>>>(
        (const bf16*)p_ffb, NN, 1024, (const bf16*)p_wtf2, f2b, p_ff2, 256, 0, 0);

    // 10. LN2(h1 + ff) -> output
    k_ln<<<(NN + 7) / 8, 256>>>((const float*)p_h1, (const float*)p_ff2,
                                ln2_g, ln2_b, out, nullptr, NN);
}

// round 16
// speedup vs baseline: 1.6540x; 1.0575x over previous
#include <cuda_runtime.h>
#include <cuda_bf16.h>
#include <math.h>
#include <stdint.h>

// Problem constants
#define NN_MAX 50000
#define NE_MAX 400000
#define DIM 256
#define NHEAD 4

typedef __nv_bfloat16 bf16;

// ---------------- scratch (static __device__ arrays, no allocation) -------
__device__ bf16     g_hn_bf[NN_MAX * 256];       // h_n bf16
__device__ bf16     g_he_bf[NE_MAX * 256];       // h_e bf16
__device__ bf16     g_node_projh[NN_MAX * 768];  // [q|k|v] per node
__device__ bf16     g_edge_projh[NE_MAX * 768];  // [q|k|v] per edge
__device__ bf16     g_att_bf[NN_MAX * DIM];      // attention output (feeds Wo)
__device__ float    g_tmp[NN_MAX * DIM];         // after Wo
__device__ float    g_h1[NN_MAX * DIM];          // after LN1 (fp32)
__device__ bf16     g_h1_bf[NN_MAX * DIM];       // after LN1 (bf16)
__device__ bf16     g_ff_bf[NN_MAX * 1024];      // after FFN1+gelu (bf16)
__device__ float    g_ff2[NN_MAX * DIM];         // after FFN2
// CSR attention scratch
__device__ int      g_cnt[NN_MAX];               // edges per src
__device__ int      g_fill[NN_MAX];              // fill cursors
__device__ int      g_off[NN_MAX + 1];           // exclusive offsets
__device__ bf16     g_wv[(size_t)NE_MAX * 256];  // ex * (vn+ve) per edge slot
__device__ float    g_ex[NE_MAX * 4];            // ex per (slot, head)
// transposed weights [N][K] K-major, bf16 (built per launch)
__device__ bf16     g_wt_n[768 * 256];
__device__ bf16     g_wt_e[768 * 256];
__device__ bf16     g_wt_wo[256 * 256];
__device__ bf16     g_wt_f1[1024 * 256];
__device__ bf16     g_wt_f2[256 * 1024];
__device__ float    g_bias_n[768];

// ---------------- helpers --------------------------------------------------
__device__ __forceinline__ float gelu_exact(float x) {
    return 0.5f * x * (1.0f + erff(x * 0.70710678118654752440f));
}
__device__ __forceinline__ unsigned pack_bf16x2(float x, float y) {
    __nv_bfloat162 h = __float22bfloat162_rn(make_float2(x, y));
    return reinterpret_cast<unsigned&>(h);
}
__device__ __forceinline__ void mma_bf16(float* c, const unsigned* a,
                                         const unsigned* b) {
    asm volatile(
        "mma.sync.aligned.m16n8k16.row.col.f32.bf16.bf16.f32 "
        "{%0,%1,%2,%3}, {%4,%5,%6,%7}, {%8,%9}, {%0,%1,%2,%3};"
        : "+f"(c[0]), "+f"(c[1]), "+f"(c[2]), "+f"(c[3])
        : "r"(a[0]), "r"(a[1]), "r"(a[2]), "r"(a[3]),
          "r"(b[0]), "r"(b[1]));
}
__device__ __forceinline__ void ldm_x4(unsigned* r, unsigned addr) {
    asm volatile("ldmatrix.sync.aligned.m8n8.x4.shared.b16 {%0,%1,%2,%3}, [%4];"
                 : "=r"(r[0]), "=r"(r[1]), "=r"(r[2]), "=r"(r[3]) : "r"(addr));
}
__device__ __forceinline__ void cpa16(unsigned s, const void* g) {
    asm volatile("cp.async.ca.shared.global [%0], [%1], 16;"
                 :: "r"(s), "l"(g));
}
__device__ __forceinline__ void cpa_commit() {
    asm volatile("cp.async.commit_group;");
}
template <int N>
__device__ __forceinline__ void cpa_wait() {
    asm volatile("cp.async.wait_group %0;" :: "n"(N));
}

// ---------------- fused prologue kernels -----------------------------------
__device__ __forceinline__ void transpose_tile(
    const float* __restrict__ W, int ldw, int row_off,
    bf16* __restrict__ Wt, int K, int n_off, int tn, int tk) {
    __shared__ float tile[32][33];
    int n0 = tn * 32, k0 = tk * 32;
    int tx = threadIdx.x, ty = threadIdx.y;  // 32 x 8
#pragma unroll
    for (int i = ty; i < 32; i += 8)
        tile[i][tx] = W[(size_t)(row_off + k0 + i) * ldw + n0 + tx];
    __syncthreads();
#pragma unroll
    for (int i = ty; i < 32; i += 8)
        Wt[(size_t)(n_off + n0 + i) * K + k0 + tx] = __float2bfloat16(tile[tx][i]);
}

__global__ void k_prep_node(const float* __restrict__ Wq_w,
                            const float* __restrict__ Wq_b,
                            const float* __restrict__ Wkv_w,
                            const float* __restrict__ Wkv_b,
                            const float* __restrict__ Wo_w,
                            const float* __restrict__ f1w,
                            const float* __restrict__ f2w) {
    int id = blockIdx.x;
    if (id < 64) {
        transpose_tile(Wq_w, 256, 0, g_wt_n, 256, 0, id & 7, id >> 3);
    } else if (id < 192) {
        int j = id - 64;
        transpose_tile(Wkv_w, 512, 0, g_wt_n, 256, 256, j % 16, j / 16);
    } else if (id < 256) {
        int j = id - 192;
        transpose_tile(Wo_w, 256, 0, g_wt_wo, 256, 0, j & 7, j >> 3);
    } else if (id < 512) {
        int j = id - 256;
        transpose_tile(f1w, 1024, 0, g_wt_f1, 256, 0, j % 32, j / 32);
    } else if (id < 768) {
        int j = id - 512;
        transpose_tile(f2w, 256, 0, g_wt_f2, 1024, 0, j % 8, j / 8);
    } else {
        int i = (id - 768) * 256 + threadIdx.y * 32 + threadIdx.x;
        if (i < 256) g_bias_n[i] = Wq_b[i];
        else if (i < 768) g_bias_n[i] = Wkv_b[i - 256];
    }
}

__global__ void k_prep_edge(const float* __restrict__ Wq_w,
                            const float* __restrict__ Wkv_w) {
    int id = blockIdx.x;
    if (id < 64) {
        transpose_tile(Wq_w, 256, 256, g_wt_e, 256, 0, id & 7, id >> 3);
    } else {
        int j = id - 64;
        transpose_tile(Wkv_w, 512, 256, g_wt_e, 256, 256, j % 16, j / 16);
    }
}

__global__ void k_cvt(const float* __restrict__ x, bf16* __restrict__ y, int n4) {
    int i = blockIdx.x * blockDim.x + threadIdx.x;
    if (i >= n4) return;
    float4 v = *(const float4*)(x + 4 * i);
    uint2 p;
    p.x = pack_bf16x2(v.x, v.y);
    p.y = pack_bf16x2(v.z, v.w);
    *(uint2*)(y + 4 * i) = p;
}

// ---------------- CSR build (stream 3, overlaps GEMMs) ---------------------
__global__ void k_zero_cnt(int NN) {
    int i = blockIdx.x * blockDim.x + threadIdx.x;
    if (i < NN) { g_cnt[i] = 0; g_fill[i] = 0; }
}
__global__ void k_count(const int* __restrict__ ei, int NE) {
    int i = blockIdx.x * blockDim.x + threadIdx.x;
    if (i < NE) atomicAdd(&g_cnt[ei[i]], 1);
}
// one-block exclusive scan over g_cnt -> g_off (g_off[NN] = total)
__global__ __launch_bounds__(1024) void k_scan(int NN) {
    __shared__ int part[1024];
    int t = threadIdx.x;
    int chunk = (NN + 1023) / 1024;
    int beg = t * chunk;
    int end = beg + chunk; if (end > NN) end = NN;
    int s = 0;
    for (int i = beg; i < end && i < NN; i++) s += g_cnt[i];
    part[t] = s;
    __syncthreads();
    // Hillis-Steele inclusive scan
    for (int off = 1; off < 1024; off <<= 1) {
        int v = (t >= off) ? part[t - off] : 0;
        __syncthreads();
        part[t] += v;
        __syncthreads();
    }
    int run = part[t] - s;   // exclusive prefix of this chunk
    for (int i = beg; i < end && i < NN; i++) {
        g_off[i] = run;
        run += g_cnt[i];
    }
    if (t == 1023) g_off[NN] = part[1023];
}

// ---------------- bf16 tensor-core GEMM (4-stage cp.async + ldmatrix) ------
#define RS 80                        // bytes per smem row (64 data + 16 pad)
#define MSTG (128 * RS)              // one matrix stage: 10240 B
#define PSTG (2 * MSTG)              // A+B stage pair: 20480 B
#define NSTAGE 4
#define GSM_BYTES (NSTAGE * PSTG)    // 81920 B dynamic smem

__global__ __launch_bounds__(256)
void tgemm_bf(const bf16* __restrict__ A, int M, int K,
              const bf16* __restrict__ Wt, const float* __restrict__ bias,
              void* __restrict__ C, int N, int act, int obf16) {
    extern __shared__ char dsm[];
    const unsigned base = (unsigned)__cvta_generic_to_shared(dsm);

    const int cb = blockIdx.x * 128;
    const int rb = blockIdx.y * 128;

    const int t    = threadIdx.x;
    const int lane = t & 31;
    const int wid  = t >> 5;
    const int wm   = wid & 1;
    const int wn   = wid >> 1;
    const int g    = lane >> 2;
    const int tg   = lane & 3;

    float acc[4][4][4];
#pragma unroll
    for (int mt = 0; mt < 4; mt++)
#pragma unroll
        for (int nt = 0; nt < 4; nt++)
#pragma unroll
            for (int r = 0; r < 4; r++) acc[mt][nt][r] = 0.0f;

    const int NT = K / 32;
    const int s_row = t >> 1;
    const int s_c   = (t & 1) * 2;

    auto stage = [&](int kt) {
        unsigned sb = base + (kt & (NSTAGE - 1)) * PSTG;
        int k0 = kt * 32;
        int ga = rb + s_row; if (ga >= M) ga = M - 1;
#pragma unroll
        for (int cc = 0; cc < 2; cc++) {
            int c = s_c + cc;
            cpa16(sb + s_row * RS + c * 16, A + (size_t)ga * K + k0 + c * 8);
            cpa16(sb + MSTG + s_row * RS + c * 16,
                  Wt + (size_t)(cb + s_row) * K + k0 + c * 8);
        }
        cpa_commit();
    };

    stage(0);
    if (NT > 1) stage(1); else cpa_commit();
    if (NT > 2) stage(2); else cpa_commit();

    // A: x4 per (mt, ko): lanes 0-15 rows, 16-31 second 16B half
    const unsigned aOff = (lane & 15) * RS + (lane >> 4) * 16;
    // B paired x4: matrices = (nt, k0-7), (nt, k8-15), (nt+1, k0-7), (nt+1, k8-15)
    const unsigned bOff4 = (lane & 7) * RS + ((lane >> 3) & 1) * 16
                         + (lane >> 4) * 8 * RS;

    for (int kt = 0; kt < NT; kt++) {
        cpa_wait<2>();
        __syncthreads();
        if (kt + 3 < NT) stage(kt + 3); else cpa_commit();

        const unsigned aB = base + (kt & (NSTAGE - 1)) * PSTG;
        const unsigned bB = aB + MSTG;
#pragma unroll
        for (int ko = 0; ko < 2; ko++) {
            unsigned a[4][4], b[4][2];
#pragma unroll
            for (int mt = 0; mt < 4; mt++)
                ldm_x4(a[mt], aB + (wm * 64 + mt * 16) * RS + aOff + ko * 32);
#pragma unroll
            for (int p = 0; p < 2; p++) {
                unsigned r4[4];
                ldm_x4(r4, bB + (wn * 32 + p * 16) * RS + bOff4 + ko * 32);
                b[2 * p][0] = r4[0]; b[2 * p][1] = r4[1];
                b[2 * p + 1][0] = r4[2]; b[2 * p + 1][1] = r4[3];
            }
#pragma unroll
            for (int mt = 0; mt < 4; mt++)
#pragma unroll
                for (int nt = 0; nt < 4; nt++)
                    mma_bf16(acc[mt][nt], a[mt], b[nt]);
        }
    }

#pragma unroll
    for (int mt = 0; mt < 4; mt++) {
        int r0 = rb + wm * 64 + mt * 16 + g;
#pragma unroll
        for (int nt = 0; nt < 4; nt++) {
            int lcol = wn * 32 + nt * 8 + tg * 2;
            int ccol = cb + lcol;
            float v0 = acc[mt][nt][0], v1 = acc[mt][nt][1];
            float v2 = acc[mt][nt][2], v3 = acc[mt][nt][3];
            if (bias) {
                float bb0 = bias[lcol], bb1 = bias[lcol + 1];
                v0 += bb0; v1 += bb1; v2 += bb0; v3 += bb1;
            }
            if (act == 1) {
                v0 = gelu_exact(v0); v1 = gelu_exact(v1);
                v2 = gelu_exact(v2); v3 = gelu_exact(v3);
            }
            if (obf16) {
                bf16* Cb = (bf16*)C;
                if (r0 < M)
                    *(unsigned*)(Cb + (size_t)r0 * N + ccol) = pack_bf16x2(v0, v1);
                if (r0 + 8 < M)
                    *(unsigned*)(Cb + (size_t)(r0 + 8) * N + ccol) = pack_bf16x2(v2, v3);
            } else {
                float* Cf = (float*)C;
                if (r0 < M) {
                    Cf[(size_t)r0 * N + ccol]     = v0;
                    Cf[(size_t)r0 * N + ccol + 1] = v1;
                }
                if (r0 + 8 < M) {
                    Cf[(size_t)(r0 + 8) * N + ccol]     = v2;
                    Cf[(size_t)(r0 + 8) * N + ccol + 1] = v3;
                }
            }
        }
    }
}

// ------- edge pass: score + exp + CSR slot claim + streamed wv write ------
__global__ void k_edge_attn(const int* __restrict__ ei, int NE) {
    int w = (blockIdx.x * blockDim.x + threadIdx.x) >> 5;
    int lane = threadIdx.x & 31;
    if (w >= NE) return;
    int src = ei[w];
    int dst = ei[NE + w];
    const bf16* qn = g_node_projh + (size_t)src * 768;
    const bf16* kn = g_node_projh + (size_t)dst * 768 + 256;
    const bf16* vn = g_node_projh + (size_t)dst * 768 + 512;
    const bf16* qe = g_edge_projh + (size_t)w * 768;
    const bf16* ke = qe + 256;
    const bf16* ve = qe + 512;

    uint4 a = *(const uint4*)(qn + lane * 8);
    uint4 b = *(const uint4*)(qe + lane * 8);
    uint4 c = *(const uint4*)(kn + lane * 8);
    uint4 d = *(const uint4*)(ke + lane * 8);

    float s = 0.f;
    {
        const __nv_bfloat162* q1 = (const __nv_bfloat162*)&a;
        const __nv_bfloat162* q2 = (const __nv_bfloat162*)&b;
        const __nv_bfloat162* k1 = (const __nv_bfloat162*)&c;
        const __nv_bfloat162* k2 = (const __nv_bfloat162*)&d;
#pragma unroll
        for (int j = 0; j < 4; j++) {
            float2 x1 = __bfloat1622float2(q1[j]);
            float2 x2 = __bfloat1622float2(q2[j]);
            float2 y1 = __bfloat1622float2(k1[j]);
            float2 y2 = __bfloat1622float2(k2[j]);
            s += (x1.x + x2.x) * (y1.x + y2.x) + (x1.y + x2.y) * (y1.y + y2.y);
        }
    }
    // butterfly over the 8-lane head group: all lanes get the head's sum
#pragma unroll
    for (int off = 1; off < 8; off <<= 1)
        s += __shfl_xor_sync(0xffffffffu, s, off);

    float ex = expf(s * 0.125f);   // 1/sqrt(64); scores O(1), no max needed
    int h = lane >> 3;

    // claim CSR slot (one atomic per edge)
    int slot;
    if (lane == 0) slot = g_off[src] + atomicAdd(&g_fill[src], 1);
    slot = __shfl_sync(0xffffffffu, slot, 0);

    if ((lane & 7) == 0) g_ex[slot * 4 + h] = ex;

    uint4 va = *(const uint4*)(vn + lane * 8);
    uint4 vb = *(const uint4*)(ve + lane * 8);
    const __nv_bfloat162* v1 = (const __nv_bfloat162*)&va;
    const __nv_bfloat162* v2 = (const __nv_bfloat162*)&vb;
    uint4 outw;
    __nv_bfloat162* ow = (__nv_bfloat162*)&outw;
#pragma unroll
    for (int j = 0; j < 4; j++) {
        float2 x1 = __bfloat1622float2(v1[j]);
        float2 x2 = __bfloat1622float2(v2[j]);
        ow[j] = __float22bfloat162_rn(
            make_float2(ex * (x1.x + x2.x), ex * (x1.y + x2.y)));
    }
    *(uint4*)(g_wv + (size_t)slot * 256 + lane * 8) = outw;
}

// ------- node gather: fp32 accumulate over CSR range, normalize, write ----
__global__ void k_gather(int NN) {
    int node = (blockIdx.x * blockDim.x + threadIdx.x) >> 5;
    int lane = threadIdx.x & 31;
    if (node >= NN) return;
    int beg = g_off[node];
    int end = g_off[node + 1];
    int h = lane >> 3;
    float acc[8] = {0.f, 0.f, 0.f, 0.f, 0.f, 0.f, 0.f, 0.f};
    float den = 0.f;
    for (int sIdx = beg; sIdx < end; sIdx++) {
        den += g_ex[sIdx * 4 + h];
        uint4 wv = *(const uint4*)(g_wv + (size_t)sIdx * 256 + lane * 8);
        const __nv_bfloat162* ww = (const __nv_bfloat162*)&wv;
#pragma unroll
        for (int j = 0; j < 4; j++) {
            float2 v = __bfloat1622float2(ww[j]);
            acc[2 * j]     += v.x;
            acc[2 * j + 1] += v.y;
        }
    }
    float inv = (den > 0.f) ? (1.f / den) : 0.f;
    uint4 outw;
    unsigned* ow = (unsigned*)&outw;
#pragma unroll
    for (int j = 0; j < 4; j++)
        ow[j] = pack_bf16x2(acc[2 * j] * inv, acc[2 * j + 1] * inv);
    *(uint4*)(g_att_bf + (size_t)node * 256 + lane * 8) = outw;
}

// ------------- layernorm (warp per row of 256), optional bf16 copy --------
__global__ void k_ln(const float* __restrict__ x, const float* __restrict__ res,
                     const float* __restrict__ g, const float* __restrict__ b,
                     float* __restrict__ out, bf16* __restrict__ out_bf, int M) {
    int w = (blockIdx.x * blockDim.x + threadIdx.x) >> 5;
    int lane = threadIdx.x & 31;
    if (w >= M) return;
    float v[8];
    float s = 0.f;
#pragma unroll
    for (int j = 0; j < 8; j++) {
        int i = lane + 32 * j;
        v[j] = x[(size_t)w * 256 + i] + res[(size_t)w * 256 + i];
        s += v[j];
    }
#pragma unroll
    for (int off = 16; off; off >>= 1) s += __shfl_xor_sync(0xffffffffu, s, off);
    float mu = s * (1.0f / 256.0f);
    float q = 0.f;
#pragma unroll
    for (int j = 0; j < 8; j++) { float d = v[j] - mu; q += d * d; }
#pragma unroll
    for (int off = 16; off; off >>= 1) q += __shfl_xor_sync(0xffffffffu, q, off);
    float rstd = rsqrtf(q * (1.0f / 256.0f) + 1e-5f);
#pragma unroll
    for (int j = 0; j < 8; j++) {
        int i = lane + 32 * j;
        float y = (v[j] - mu) * rstd * g[i] + b[i];
        out[(size_t)w * 256 + i] = y;
        if (out_bf) out_bf[(size_t)w * 256 + i] = __float2bfloat16(y);
    }
}

// ---------------- host launch ----------------------------------------------
extern "C" void kernel_launch(void* const* d_in, const int* in_sizes, int n_in,
                              void* d_out, int out_size) {
    const float* h_n   = (const float*)d_in[0];
    const float* h_e   = (const float*)d_in[1];
    const int*   ei    = (const int*)d_in[2];   // int32 (JAX x64 disabled)
    const float* Wq_w  = (const float*)d_in[3];
    const float* Wq_b  = (const float*)d_in[4];
    const float* Wkv_w = (const float*)d_in[5];
    const float* Wkv_b = (const float*)d_in[6];
    const float* Wo_w  = (const float*)d_in[7];
    const float* Wo_b  = (const float*)d_in[8];
    const float* ln1_g = (const float*)d_in[9];
    const float* ln1_b = (const float*)d_in[10];
    const float* f1w   = (const float*)d_in[11];
    const float* f1b   = (const float*)d_in[12];
    const float* f2w   = (const float*)d_in[13];
    const float* f2b   = (const float*)d_in[14];
    const float* ln2_g = (const float*)d_in[15];
    const float* ln2_b = (const float*)d_in[16];
    float* out = (float*)d_out;

    int NN = in_sizes[0] / DIM;
    int NE = in_sizes[1] / DIM;

    static int inited = 0;
    static cudaStream_t s2, s3;
    static cudaEvent_t evFork, evJoin2, evJoin3;
    if (!inited) {
        cudaFuncSetAttribute(tgemm_bf,
                             cudaFuncAttributeMaxDynamicSharedMemorySize,
                             GSM_BYTES);
        cudaStreamCreateWithFlags(&s2, cudaStreamNonBlocking);
        cudaStreamCreateWithFlags(&s3, cudaStreamNonBlocking);
        cudaEventCreateWithFlags(&evFork, cudaEventDisableTiming);
        cudaEventCreateWithFlags(&evJoin2, cudaEventDisableTiming);
        cudaEventCreateWithFlags(&evJoin3, cudaEventDisableTiming);
        inited = 1;
    }

    void *p_hn, *p_he, *p_nph, *p_eph, *p_attb, *p_tmp;
    void *p_h1, *p_h1b, *p_ffb, *p_ff2;
    void *p_wtn, *p_wte, *p_wtwo, *p_wtf1, *p_wtf2, *p_bn;
    cudaGetSymbolAddress(&p_hn, g_hn_bf);
    cudaGetSymbolAddress(&p_he, g_he_bf);
    cudaGetSymbolAddress(&p_nph, g_node_projh);
    cudaGetSymbolAddress(&p_eph, g_edge_projh);
    cudaGetSymbolAddress(&p_attb, g_att_bf);
    cudaGetSymbolAddress(&p_tmp, g_tmp);
    cudaGetSymbolAddress(&p_h1, g_h1);
    cudaGetSymbolAddress(&p_h1b, g_h1_bf);
    cudaGetSymbolAddress(&p_ffb, g_ff_bf);
    cudaGetSymbolAddress(&p_ff2, g_ff2);
    cudaGetSymbolAddress(&p_wtn, g_wt_n);
    cudaGetSymbolAddress(&p_wte, g_wt_e);
    cudaGetSymbolAddress(&p_wtwo, g_wt_wo);
    cudaGetSymbolAddress(&p_wtf1, g_wt_f1);
    cudaGetSymbolAddress(&p_wtf2, g_wt_f2);
    cudaGetSymbolAddress(&p_bn, g_bias_n);

    dim3 tb(32, 8);

    // ---- fork ----
    cudaEventRecord(evFork, 0);
    cudaStreamWaitEvent(s2, evFork, 0);
    cudaStreamWaitEvent(s3, evFork, 0);

    // node branch (s2): weight prep, h_n cvt, node projections
    k_prep_node<<<771, tb, 0, s2>>>(Wq_w, Wq_b, Wkv_w, Wkv_b, Wo_w, f1w, f2w);
    k_cvt<<<(NN * 64 + 255) / 256, 256, 0, s2>>>(h_n, (bf16*)p_hn, NN * 64);
    tgemm_bf<<<dim3(6, (NN + 127) / 128), 256, GSM_BYTES, s2>>>(
        (const bf16*)p_hn, NN, 256, (const bf16*)p_wtn, (const float*)p_bn,
        p_nph, 768, 0, 1);
    cudaEventRecord(evJoin2, s2);

    // CSR branch (s3): zero counters, count, scan
    k_zero_cnt<<<(NN + 255) / 256, 256, 0, s3>>>(NN);
    k_count<<<(NE + 255) / 256, 256, 0, s3>>>(ei, NE);
    k_scan<<<1, 1024, 0, s3>>>(NN);
    cudaEventRecord(evJoin3, s3);

    // edge branch (stream 0, critical path)
    k_prep_edge<<<192, tb>>>(Wq_w, Wkv_w);
    k_cvt<<<(NE * 64 + 255) / 256, 256>>>(h_e, (bf16*)p_he, NE * 64);
    tgemm_bf<<<dim3(6, (NE + 127) / 128), 256, GSM_BYTES>>>(
        (const bf16*)p_he, NE, 256, (const bf16*)p_wte, nullptr, p_eph, 768, 0, 1);

    // ---- join ----
    cudaStreamWaitEvent(0, evJoin2, 0);
    cudaStreamWaitEvent(0, evJoin3, 0);

    // 4. edge pass: scores + exp + CSR streamed wv (one atomic per edge)
    k_edge_attn<<<(NE + 7) / 8, 256>>>(ei, NE);

    // 5. node gather: fp32 accumulate + normalize -> att_bf
    k_gather<<<(NN + 7) / 8, 256>>>(NN);

    // 6. output projection Wo (fp32 out)
    tgemm_bf<<<dim3(2, (NN + 127) / 128), 256, GSM_BYTES>>>(
        (const bf16*)p_attb, NN, 256, (const bf16*)p_wtwo, Wo_b, p_tmp, 256, 0, 0);

    // 7. LN1(h_n + attn_proj) -> fp32 + bf16
    k_ln<<<(NN + 7) / 8, 256>>>(h_n, (const float*)p_tmp, ln1_g, ln1_b,
                                (float*)p_h1, (bf16*)p_h1b, NN);

    // 8. FFN1 + exact GELU -> bf16
    tgemm_bf<<<dim3(8, (NN + 127) / 128), 256, GSM_BYTES>>>(
        (const bf16*)p_h1b, NN, 256, (const bf16*)p_wtf1, f1b, p_ffb, 1024, 1, 1);

    // 9. FFN2 (fp32 out, K=1024)
    tgemm_bf<<<dim3(2, (NN + 127) / 128), 256, GSM_BYTES>>>(
        (const bf16*)p_ffb, NN, 1024, (const bf16*)p_wtf2, f2b, p_ff2, 256, 0, 0);

    // 10. LN2(h1 + ff) -> output
    k_ln<<<(NN + 7) / 8, 256>>>((const float*)p_h1, (const float*)p_ff2,
                                ln2_g, ln2_b, out, nullptr, NN);
}